// round 14
// baseline (speedup 1.0000x reference)
#include <cuda_runtime.h>
#include <cuda_fp16.h>
#include <math.h>
#include <stdint.h>

#define BSZ 2
#define TLEN 2048
#define DM 1024
#define NH 16
#define DK 64
#define NR 17
#define L2E 1.4426950408889634f

// ---------------- scratch (device globals; no allocation allowed) ----------
__device__ __align__(128) __half g_hx[3][(size_t)BSZ*TLEN*DM]; // fp16 query/key/value inputs
__device__ __align__(128) __half g_hw[4][DM*DM];               // fp16 w_q,w_k,w_v,w_o
__device__ __align__(128) __half g_q[(size_t)BSZ*NH*TLEN*DK];  // scaled by 1/8
__device__ __align__(128) __half g_k[(size_t)BSZ*NH*TLEN*DK];
__device__ __align__(128) __half g_v[(size_t)BSZ*NH*TLEN*DK];
__device__ __align__(128) __half g_x[(size_t)BSZ*TLEN*DM];     // attention out (fp16)

// ---------------- asm helpers ----------------------------------------------
__device__ __forceinline__ uint32_t smem_u32(const void* p) {
    uint32_t a;
    asm("{ .reg .u64 t; cvta.to.shared.u64 t, %1; cvt.u32.u64 %0, t; }"
        : "=r"(a) : "l"(p));
    return a;
}
__device__ __forceinline__ void cp16(uint32_t dst, const void* src) {
    asm volatile("cp.async.cg.shared.global [%0], [%1], 16;"
                 :: "r"(dst), "l"(src));
}
#define CP_COMMIT() asm volatile("cp.async.commit_group;" ::: "memory")
#define CP_WAIT(n)  asm volatile("cp.async.wait_group %0;" :: "n"(n) : "memory")

__device__ __forceinline__ void ldsm_x4(uint32_t* r, uint32_t a) {
    asm volatile("ldmatrix.sync.aligned.m8n8.x4.shared.b16 {%0,%1,%2,%3}, [%4];"
                 : "=r"(r[0]), "=r"(r[1]), "=r"(r[2]), "=r"(r[3]) : "r"(a));
}
__device__ __forceinline__ void ldsm_x4t(uint32_t* r, uint32_t a) {
    asm volatile("ldmatrix.sync.aligned.m8n8.x4.trans.shared.b16 {%0,%1,%2,%3}, [%4];"
                 : "=r"(r[0]), "=r"(r[1]), "=r"(r[2]), "=r"(r[3]) : "r"(a));
}
// D(16x8,f32) += A(16x16,f16) * B(16x8,f16)
__device__ __forceinline__ void mma16(float* d, const uint32_t* a, uint32_t b0, uint32_t b1) {
    asm volatile(
        "mma.sync.aligned.m16n8k16.row.col.f32.f16.f16.f32 "
        "{%0,%1,%2,%3}, {%4,%5,%6,%7}, {%8,%9}, {%0,%1,%2,%3};"
        : "+f"(d[0]), "+f"(d[1]), "+f"(d[2]), "+f"(d[3])
        : "r"(a[0]), "r"(a[1]), "r"(a[2]), "r"(a[3]), "r"(b0), "r"(b1));
}
__device__ __forceinline__ uint32_t packh2(float hi, float lo) {
    uint32_t r;
    asm("cvt.rn.f16x2.f32 %0, %1, %2;" : "=r"(r) : "f"(hi), "f"(lo));
    return r;
}
__device__ __forceinline__ uint32_t hfma2u(uint32_t a, uint32_t b, uint32_t c) {
    uint32_t d;
    asm("fma.rn.f16x2 %0, %1, %2, %3;" : "=r"(d) : "r"(a), "r"(b), "r"(c));
    return d;
}
__device__ __forceinline__ uint32_t ex2h2(uint32_t x) {
    uint32_t r;
    asm("ex2.approx.f16x2 %0, %1;" : "=r"(r) : "r"(x));
    return r;
}
__device__ __forceinline__ float2 h22f2(uint32_t h) {
    __half2 hh = *(__half2*)&h;
    return __half22float2(hh);
}

// ---------------- fp32 -> fp16 conversion pre-pass --------------------------
__global__ __launch_bounds__(256) void cvt_x3(
    const float* __restrict__ q, const float* __restrict__ k, const float* __restrict__ v)
{
    const float* src = blockIdx.y == 0 ? q : blockIdx.y == 1 ? k : v;
    __half* dst = g_hx[blockIdx.y];
    size_t i = ((size_t)blockIdx.x * 256 + threadIdx.x) * 4;
    float4 f = *(const float4*)(src + i);
    __half2* d = (__half2*)(dst + i);
    d[0] = __floats2half2_rn(f.x, f.y);
    d[1] = __floats2half2_rn(f.z, f.w);
}
__global__ __launch_bounds__(256) void cvt_w4(
    const float* __restrict__ w0, const float* __restrict__ w1,
    const float* __restrict__ w2, const float* __restrict__ w3)
{
    const float* src = blockIdx.y == 0 ? w0 : blockIdx.y == 1 ? w1
                     : blockIdx.y == 2 ? w2 : w3;
    __half* dst = g_hw[blockIdx.y];
    size_t i = ((size_t)blockIdx.x * 256 + threadIdx.x) * 4;
    float4 f = *(const float4*)(src + i);
    __half2* d = (__half2*)(dst + i);
    d[0] = __floats2half2_rn(f.x, f.y);
    d[1] = __floats2half2_rn(f.z, f.w);
}

// ======= fp16 GEMM core: 128x256 tile, 16 warps (512 thr), 3-stage =========
#define GA_ST 5120      // halves per A stage (128 x 40)
#define GB_ST 8448      // halves per B stage (32 x 264)
#define G_SMEM ((3 * GA_ST + 3 * GB_ST) * 2)

template <typename EpiFn>
__device__ __forceinline__ void gemm_body16(
    const __half* __restrict__ X, const __half* __restrict__ W,
    int m0, int n0, EpiFn epi)
{
    extern __shared__ __half gsm[];
    __half* As = gsm;
    __half* Bs = gsm + 3 * GA_ST;
    const uint32_t aB = smem_u32(As);
    const uint32_t bB = smem_u32(Bs);
    const int tid = threadIdx.x;
    const int lane = tid & 31, wid = tid >> 5;
    const int g = lane >> 2, t = lane & 3;
    const int mbase = (wid & 3) * 32, nbase = (wid >> 2) * 64;

    float acc[2][8][4];
#pragma unroll
    for (int mt = 0; mt < 2; mt++)
#pragma unroll
        for (int nt = 0; nt < 8; nt++)
#pragma unroll
            for (int u = 0; u < 4; u++) acc[mt][nt][u] = 0.f;

    auto issue = [&](int kt, int st) {
        // A: 128 rows x 32 cols -> 512 cp16 (one per thread)
        {
            int row = tid >> 2, off = (tid & 3) * 8;
            cp16(aB + (uint32_t)((st * GA_ST + row * 40 + off) * 2),
                 X + (size_t)(m0 + row) * DM + kt * 32 + off);
        }
        // B: 32 rows x 256 cols -> 1024 cp16 (two per thread)
#pragma unroll
        for (int i = 0; i < 2; i++) {
            int idx = tid + 512 * i;
            int kr = idx >> 5, noff = (idx & 31) * 8;
            cp16(bB + (uint32_t)((st * GB_ST + kr * 264 + noff) * 2),
                 W + (size_t)(kt * 32 + kr) * DM + n0 + noff);
        }
        CP_COMMIT();
    };

    const int arow = (lane & 15);
    const int acol = ((lane >> 4) << 3);
    const int bk   = (lane & 15);
    const int bn   = ((lane >> 4) << 3);

    issue(0, 0);
    issue(1, 1);
    for (int kt = 0; kt < 32; kt++) {
        const int st = kt - (kt / 3) * 3;
        __syncthreads();
        if (kt + 2 < 32) issue(kt + 2, (kt + 2) % 3);
        else CP_COMMIT();
        CP_WAIT(2);
        __syncthreads();

        uint32_t a[2][2][4];
#pragma unroll
        for (int mt = 0; mt < 2; mt++)
#pragma unroll
            for (int kh = 0; kh < 2; kh++)
                ldsm_x4(a[mt][kh],
                        aB + (uint32_t)((st * GA_ST
                              + (mbase + mt * 16 + arow) * 40
                              + kh * 16 + acol) * 2));
#pragma unroll
        for (int kh = 0; kh < 2; kh++) {
#pragma unroll
            for (int p = 0; p < 4; p++) {
                uint32_t bf[4];
                ldsm_x4t(bf, bB + (uint32_t)((st * GB_ST
                                  + (kh * 16 + bk) * 264
                                  + nbase + p * 16 + bn) * 2));
                mma16(acc[0][2 * p],     a[0][kh], bf[0], bf[1]);
                mma16(acc[0][2 * p + 1], a[0][kh], bf[2], bf[3]);
                mma16(acc[1][2 * p],     a[1][kh], bf[0], bf[1]);
                mma16(acc[1][2 * p + 1], a[1][kh], bf[2], bf[3]);
            }
        }
    }
    epi(acc, mbase, nbase, g, t);
}

// ---------------- fused Q/K/V projection GEMM ------------------------------
__global__ __launch_bounds__(512, 1) void proj_gemm_tc(
    const float* __restrict__ Bq, const float* __restrict__ Bk, const float* __restrict__ Bv)
{
    const __half* X = g_hx[blockIdx.z];
    const __half* W = g_hw[blockIdx.z];
    const float* Bi = blockIdx.z == 0 ? Bq : blockIdx.z == 1 ? Bk : Bv;
    __half* Out = blockIdx.z == 0 ? g_q : blockIdx.z == 1 ? g_k : g_v;
    const float scale = blockIdx.z == 0 ? 0.125f : 1.0f;
    const int m0 = blockIdx.y * 128, n0 = blockIdx.x * 256;

    gemm_body16(X, W, m0, n0,
        [&](float acc[2][8][4], int mbase, int nbase, int g, int t) {
#pragma unroll
            for (int mt = 0; mt < 2; mt++) {
#pragma unroll
                for (int rr = 0; rr < 2; rr++) {
                    int m = m0 + mbase + mt * 16 + g + 8 * rr;
                    int bb = m >> 11, t_ = m & (TLEN - 1);
#pragma unroll
                    for (int nt = 0; nt < 8; nt++) {
                        int n = n0 + nbase + nt * 8 + 2 * t;
                        int h = n >> 6, d = n & 63;
                        float v0 = (acc[mt][nt][rr * 2 + 0] + Bi[n]) * scale;
                        float v1 = (acc[mt][nt][rr * 2 + 1] + Bi[n + 1]) * scale;
                        __half2* dst = (__half2*)(Out
                            + (((size_t)(bb * NH + h)) * TLEN + t_) * DK + d);
                        *dst = __floats2half2_rn(v0, v1);
                    }
                }
            }
        });
}

// ---------------- output projection GEMM (writes fp32 result) --------------
__global__ __launch_bounds__(512, 1) void out_gemm_tc(
    const float* __restrict__ Bi, float* __restrict__ Out)
{
    const int m0 = blockIdx.y * 128, n0 = blockIdx.x * 256;
    gemm_body16(g_x, g_hw[3], m0, n0,
        [&](float acc[2][8][4], int mbase, int nbase, int g, int t) {
#pragma unroll
            for (int mt = 0; mt < 2; mt++) {
#pragma unroll
                for (int rr = 0; rr < 2; rr++) {
                    int m = m0 + mbase + mt * 16 + g + 8 * rr;
#pragma unroll
                    for (int nt = 0; nt < 8; nt++) {
                        int n = n0 + nbase + nt * 8 + 2 * t;
                        float2 v;
                        v.x = acc[mt][nt][rr * 2 + 0] + Bi[n];
                        v.y = acc[mt][nt][rr * 2 + 1] + Bi[n + 1];
                        *(float2*)(Out + (size_t)m * DM + n) = v;
                    }
                }
            }
        });
}

// =============== fp16 HMMA flash attention with relative positions =========
// Br=128 (8 warps x 16 rows), Bc=64. K dbl-buffered, V single-buffered with
// late wait; f16x2 ex2 softmax on tail blocks, exact fp32 near diagonal.
#define AT_Q    0                     // 128 x 72 halves
#define AT_K    18432                 // 2 x 64 x 72 halves
#define AT_V    36864                 // 64 x 72 halves
#define AT_TBL  46080                 // 32 x 72 halves (rpr_key, rows 17.. zeroed)
#define AT_QR   50688                 // 128 x 17 f32 (scaled by L2E)
#define AT_RVT  59392                 // 17 x 64 f32
#define AT_SI   63744                 // 128 x 17 f32
#define AT_SMEM_BYTES 72448
#define NIT (TLEN / 64)

__global__ __launch_bounds__(256, 2) void flash_attn_tc(
    const float* __restrict__ tabk, const float* __restrict__ rvt_g)
{
    extern __shared__ char sm8[];
    const uint32_t qB = smem_u32(sm8) + AT_Q;
    const uint32_t kB = smem_u32(sm8) + AT_K;
    const uint32_t vB = smem_u32(sm8) + AT_V;
    const uint32_t tB = smem_u32(sm8) + AT_TBL;
    float* qrs  = (float*)(sm8 + AT_QR);
    float* rvts = (float*)(sm8 + AT_RVT);
    float* sInt = (float*)(sm8 + AT_SI);

    const int tid = threadIdx.x;
    const int wid = tid >> 5, lane = tid & 31;
    const int g = lane >> 2, t = lane & 3;
    const int b = blockIdx.z, h = blockIdx.y;
    const int i0 = blockIdx.x * 128;
    const size_t bh = (size_t)(b * NH + h) * TLEN;

    const int r0 = wid * 16 + g;
    const int r1 = r0 + 8;
    const int gi0 = i0 + r0, gi1 = i0 + r1;

    const __half* kgl = g_k + bh * DK;
    const __half* vgl = g_v + bh * DK;

    auto issueK = [&](int it, int st) {
        const __half* kp = kgl + (size_t)(it * 64) * DK;
#pragma unroll
        for (int i = 0; i < 2; i++) {
            int idx = tid + 256 * i;
            int row = idx >> 3, off = (idx & 7) * 8;
            cp16(kB + (uint32_t)((st * 4608 + row * 72 + off) * 2), kp + row * 64 + off);
        }
        CP_COMMIT();
    };
    auto issueV = [&](int it) {
        const __half* vp = vgl + (size_t)(it * 64) * DK;
#pragma unroll
        for (int i = 0; i < 2; i++) {
            int idx = tid + 256 * i;
            int row = idx >> 3, off = (idx & 7) * 8;
            cp16(vB + (uint32_t)((row * 72 + off) * 2), vp + row * 64 + off);
        }
        CP_COMMIT();
    };

    // prologue: Q group, K0 group; scalar tables
    {
        const __half* qp = g_q + (bh + i0) * DK;
#pragma unroll
        for (int i = 0; i < 4; i++) {
            int idx = tid + 256 * i;
            int row = idx >> 3, off = (idx & 7) * 8;
            cp16(qB + (uint32_t)((row * 72 + off) * 2), qp + row * 64 + off);
        }
        CP_COMMIT();
    }
    issueK(0, 0);
    {
        for (int idx = tid; idx < 15 * 32; idx += 256) {
            int r = 17 + idx / 32, c = (idx & 31);
            *(uint32_t*)(sm8 + AT_TBL + ((size_t)r * 72 + c * 2) * 2) = 0u;
        }
        for (int idx = tid; idx < 17 * 32; idx += 256) {
            int r = idx / 32, c2 = (idx & 31) * 2;
            float2 f = *(const float2*)(tabk + r * 64 + c2);
            *(__half2*)(sm8 + AT_TBL + ((size_t)r * 72 + c2) * 2) = __floats2half2_rn(f.x, f.y);
        }
        for (int idx = tid; idx < NR * 64; idx += 256)  rvts[idx] = rvt_g[idx];
        for (int idx = tid; idx < 128 * 17; idx += 256) sInt[idx] = 0.f;
    }
    CP_WAIT(1);            // Q arrived (K0 may still be in flight)
    __syncthreads();       // Q + table visible

    const int qrow = wid * 16 + (lane & 15);
    const int qcol = ((lane >> 4) << 3);
    const int skey = ((lane >> 4) << 3) + (lane & 7);
    const int sd   = (lane & 8);
    const int vkey = (lane & 15);
    const int vd   = ((lane >> 4) << 3);

    uint32_t qa[4][4];
#pragma unroll
    for (int kh = 0; kh < 4; kh++)
        ldsm_x4(qa[kh], qB + (uint32_t)((qrow * 72 + kh * 16 + qcol) * 2));

    // qr = Q @ table^T  (n padded to 32; cols >=17 ignored)
    {
        float qracc[4][4];
#pragma unroll
        for (int p = 0; p < 4; p++)
#pragma unroll
            for (int u = 0; u < 4; u++) qracc[p][u] = 0.f;
#pragma unroll
        for (int kh = 0; kh < 4; kh++) {
#pragma unroll
            for (int p = 0; p < 2; p++) {
                uint32_t tf[4];
                ldsm_x4(tf, tB + (uint32_t)(((p * 16 + skey) * 72 + kh * 16 + sd) * 2));
                mma16(qracc[2 * p],     qa[kh], tf[0], tf[1]);
                mma16(qracc[2 * p + 1], qa[kh], tf[2], tf[3]);
            }
        }
#pragma unroll
        for (int p2 = 0; p2 < 3; p2++) {
#pragma unroll
            for (int cc = 0; cc < 2; cc++) {
                int e = p2 * 8 + 2 * t + cc;
                if (e < 17) {
                    qrs[r0 * 17 + e] = qracc[p2][cc] * L2E;
                    qrs[r1 * 17 + e] = qracc[p2][2 + cc] * L2E;
                }
            }
        }
    }
    __syncthreads();
    const float qt0_0  = qrs[r0 * 17 + 0],  qt16_0 = qrs[r0 * 17 + 16];
    const float qt0_1  = qrs[r1 * 17 + 0],  qt16_1 = qrs[r1 * 17 + 16];
    const uint32_t l2e2   = packh2(L2E, L2E);
    const uint32_t qt0h_0  = packh2(qt0_0,  qt0_0);
    const uint32_t qt16h_0 = packh2(qt16_0, qt16_0);
    const uint32_t qt0h_1  = packh2(qt0_1,  qt0_1);
    const uint32_t qt16h_1 = packh2(qt16_1, qt16_1);

    float oacc[8][4];
#pragma unroll
    for (int nt = 0; nt < 8; nt++)
#pragma unroll
        for (int u = 0; u < 4; u++) oacc[nt][u] = 0.f;
    float lsum0 = 0.f, lsum1 = 0.f;
    float b0s0 = 0.f, b0s1 = 0.f, b16s0 = 0.f, b16s1 = 0.f;

    for (int it = 0; it < NIT; it++) {
        const int j0 = it * 64;
        __syncthreads();                 // V buffer + K stage reuse safe
        issueV(it);
        if (it + 1 < NIT) { issueK(it + 1, (it + 1) & 1); CP_WAIT(2); }
        else              { CP_WAIT(1); }
        __syncthreads();                 // K(it) ready

        const uint32_t kS = kB + (uint32_t)((it & 1) * 4608 * 2);

        // S = Q @ K^T
        float sacc[8][4];
#pragma unroll
        for (int nt = 0; nt < 8; nt++)
#pragma unroll
            for (int u = 0; u < 4; u++) sacc[nt][u] = 0.f;
#pragma unroll
        for (int kh = 0; kh < 4; kh++) {
#pragma unroll
            for (int p = 0; p < 4; p++) {
                uint32_t bf[4];
                ldsm_x4(bf, kS + (uint32_t)(((p * 16 + skey) * 72
                                 + kh * 16 + sd) * 2));
                mma16(sacc[2 * p],     qa[kh], bf[0], bf[1]);
                mma16(sacc[2 * p + 1], qa[kh], bf[2], bf[3]);
            }
        }

        // softmax; f16x2 ex2 on tail blocks, exact fp32 near diagonal
        uint32_t ep[8][2];
        // ---- row 0
        if (j0 + 71 <= gi0 || j0 >= gi0 + 8) {
            const bool left = (j0 + 71 <= gi0);
            const uint32_t qth = left ? qt0h_0 : qt16h_0;
            float bs = 0.f;
#pragma unroll
            for (int nt = 0; nt < 8; nt++) {
                uint32_t ph = packh2(sacc[nt][1], sacc[nt][0]);
                uint32_t pe = ex2h2(hfma2u(ph, l2e2, qth));
                ep[nt][0] = pe;
                float2 pf = h22f2(pe);
                bs += pf.x + pf.y;
            }
            lsum0 += bs;
            if (left) b0s0 += bs; else b16s0 += bs;
        } else {
#pragma unroll
            for (int nt = 0; nt < 8; nt++) {
                float pv[2];
#pragma unroll
                for (int cc = 0; cc < 2; cc++) {
                    const int j = j0 + nt * 8 + 2 * t + cc;
                    int dd = j - gi0;
                    float add = (dd <= -8) ? qt0_0 : (dd >= 8) ? qt16_0
                                : qrs[r0 * 17 + dd + 8];
                    float p = exp2f(fmaf(sacc[nt][cc], L2E, add));
                    lsum0 += p;
                    if (dd <= -8)      b0s0 += p;
                    else if (dd >= 8)  b16s0 += p;
                    else               sInt[r0 * 17 + dd + 7] = p;
                    pv[cc] = p;
                }
                ep[nt][0] = packh2(pv[1], pv[0]);
            }
        }
        // ---- row 1
        if (j0 + 71 <= gi1 || j0 >= gi1 + 8) {
            const bool left = (j0 + 71 <= gi1);
            const uint32_t qth = left ? qt0h_1 : qt16h_1;
            float bs = 0.f;
#pragma unroll
            for (int nt = 0; nt < 8; nt++) {
                uint32_t ph = packh2(sacc[nt][3], sacc[nt][2]);
                uint32_t pe = ex2h2(hfma2u(ph, l2e2, qth));
                ep[nt][1] = pe;
                float2 pf = h22f2(pe);
                bs += pf.x + pf.y;
            }
            lsum1 += bs;
            if (left) b0s1 += bs; else b16s1 += bs;
        } else {
#pragma unroll
            for (int nt = 0; nt < 8; nt++) {
                float pv[2];
#pragma unroll
                for (int cc = 0; cc < 2; cc++) {
                    const int j = j0 + nt * 8 + 2 * t + cc;
                    int dd = j - gi1;
                    float add = (dd <= -8) ? qt0_1 : (dd >= 8) ? qt16_1
                                : qrs[r1 * 17 + dd + 8];
                    float p = exp2f(fmaf(sacc[nt][2 + cc], L2E, add));
                    lsum1 += p;
                    if (dd <= -8)      b0s1 += p;
                    else if (dd >= 8)  b16s1 += p;
                    else               sInt[r1 * 17 + dd + 7] = p;
                    pv[cc] = p;
                }
                ep[nt][1] = packh2(pv[1], pv[0]);
            }
        }

        if (it + 1 < NIT) CP_WAIT(1); else CP_WAIT(0);
        __syncthreads();                 // V(it) ready

        // O += P @ V  (ep pairs ARE the A-fragments)
#pragma unroll
        for (int ks = 0; ks < 4; ks++) {
            uint32_t pa[4];
            pa[0] = ep[2 * ks][0];
            pa[1] = ep[2 * ks][1];
            pa[2] = ep[2 * ks + 1][0];
            pa[3] = ep[2 * ks + 1][1];
#pragma unroll
            for (int p = 0; p < 4; p++) {
                uint32_t bf[4];
                ldsm_x4t(bf, vB + (uint32_t)(((ks * 16 + vkey) * 72
                                  + p * 16 + vd) * 2));
                mma16(oacc[2 * p],     pa, bf[0], bf[1]);
                mma16(oacc[2 * p + 1], pa, bf[2], bf[3]);
            }
        }
    }

    __syncthreads();
#pragma unroll
    for (int o = 1; o <= 2; o <<= 1) {
        lsum0 += __shfl_xor_sync(0xffffffffu, lsum0, o);
        lsum1 += __shfl_xor_sync(0xffffffffu, lsum1, o);
        b0s0  += __shfl_xor_sync(0xffffffffu, b0s0, o);
        b0s1  += __shfl_xor_sync(0xffffffffu, b0s1, o);
        b16s0 += __shfl_xor_sync(0xffffffffu, b16s0, o);
        b16s1 += __shfl_xor_sync(0xffffffffu, b16s1, o);
    }
    const float linv0 = 1.0f / lsum0, linv1 = 1.0f / lsum1;

    float si0[15], si1[15];
#pragma unroll
    for (int e = 0; e < 15; e++) {
        si0[e] = sInt[r0 * 17 + e];
        si1[e] = sInt[r1 * 17 + e];
    }

    __half* op0 = g_x + ((size_t)(b * TLEN) + gi0) * DM + h * DK;
    __half* op1 = g_x + ((size_t)(b * TLEN) + gi1) * DM + h * DK;
#pragma unroll
    for (int nt = 0; nt < 8; nt++) {
        const int d = nt * 8 + 2 * t;
        float e0a = b0s0 * rvts[d]     + b16s0 * rvts[16 * 64 + d];
        float e0b = b0s0 * rvts[d + 1] + b16s0 * rvts[16 * 64 + d + 1];
        float e1a = b0s1 * rvts[d]     + b16s1 * rvts[16 * 64 + d];
        float e1b = b0s1 * rvts[d + 1] + b16s1 * rvts[16 * 64 + d + 1];
#pragma unroll
        for (int e = 1; e <= 15; e++) {
            float rva = rvts[e * 64 + d], rvb = rvts[e * 64 + d + 1];
            e0a += si0[e - 1] * rva;  e0b += si0[e - 1] * rvb;
            e1a += si1[e - 1] * rva;  e1b += si1[e - 1] * rvb;
        }
        *(__half2*)(op0 + d) = __floats2half2_rn(
            (oacc[nt][0] + e0a) * linv0, (oacc[nt][1] + e0b) * linv0);
        *(__half2*)(op1 + d) = __floats2half2_rn(
            (oacc[nt][2] + e1a) * linv1, (oacc[nt][3] + e1b) * linv1);
    }
}

// ---------------- launch ----------------------------------------------------
extern "C" void kernel_launch(void* const* d_in, const int* in_sizes, int n_in,
                              void* d_out, int out_size)
{
    const float* query = (const float*)d_in[0];
    const float* key_  = (const float*)d_in[1];
    const float* value = (const float*)d_in[2];
    const float* w_q = (const float*)d_in[4];
    const float* b_q = (const float*)d_in[5];
    const float* w_k = (const float*)d_in[6];
    const float* b_k = (const float*)d_in[7];
    const float* w_v = (const float*)d_in[8];
    const float* b_v = (const float*)d_in[9];
    const float* w_o = (const float*)d_in[10];
    const float* b_o = (const float*)d_in[11];
    const float* rpr_k = (const float*)d_in[12];
    const float* rpr_v = (const float*)d_in[13];
    float* out = (float*)d_out;

    cudaFuncSetAttribute(proj_gemm_tc, cudaFuncAttributeMaxDynamicSharedMemorySize, G_SMEM);
    cudaFuncSetAttribute(out_gemm_tc,  cudaFuncAttributeMaxDynamicSharedMemorySize, G_SMEM);
    cudaFuncSetAttribute(flash_attn_tc, cudaFuncAttributeMaxDynamicSharedMemorySize, AT_SMEM_BYTES);

    cvt_x3<<<dim3((BSZ*TLEN*DM) / 1024, 3), 256>>>(query, key_, value);
    cvt_w4<<<dim3((DM*DM) / 1024, 4), 256>>>(w_q, w_k, w_v, w_o);

    proj_gemm_tc<<<dim3(DM / 256, (BSZ * TLEN) / 128, 3), 512, G_SMEM>>>(b_q, b_k, b_v);

    flash_attn_tc<<<dim3(TLEN / 128, NH, BSZ), 256, AT_SMEM_BYTES>>>(rpr_k, rpr_v);

    out_gemm_tc<<<dim3(DM / 256, (BSZ * TLEN) / 128, 1), 512, G_SMEM>>>(b_o, out);
}

// round 15
// speedup vs baseline: 1.0408x; 1.0408x over previous
#include <cuda_runtime.h>
#include <cuda_fp16.h>
#include <math.h>
#include <stdint.h>

#define BSZ 2
#define TLEN 2048
#define DM 1024
#define NH 16
#define DK 64
#define NR 17
#define L2E 1.4426950408889634f

// ---------------- scratch (device globals; no allocation allowed) ----------
__device__ __align__(128) __half g_hx[3][(size_t)BSZ*TLEN*DM]; // fp16 query/key/value inputs
__device__ __align__(128) __half g_hw[4][DM*DM];               // fp16 w_q,w_k,w_v,w_o
__device__ __align__(128) __half g_q[(size_t)BSZ*NH*TLEN*DK];  // scaled by 1/8
__device__ __align__(128) __half g_k[(size_t)BSZ*NH*TLEN*DK];
__device__ __align__(128) __half g_v[(size_t)BSZ*NH*TLEN*DK];
__device__ __align__(128) __half g_x[(size_t)BSZ*TLEN*DM];     // attention out (fp16)

// ---------------- asm helpers ----------------------------------------------
__device__ __forceinline__ uint32_t smem_u32(const void* p) {
    uint32_t a;
    asm("{ .reg .u64 t; cvta.to.shared.u64 t, %1; cvt.u32.u64 %0, t; }"
        : "=r"(a) : "l"(p));
    return a;
}
__device__ __forceinline__ void cp16(uint32_t dst, const void* src) {
    asm volatile("cp.async.cg.shared.global [%0], [%1], 16;"
                 :: "r"(dst), "l"(src));
}
#define CP_COMMIT() asm volatile("cp.async.commit_group;" ::: "memory")
#define CP_WAIT(n)  asm volatile("cp.async.wait_group %0;" :: "n"(n) : "memory")

__device__ __forceinline__ void ldsm_x4(uint32_t* r, uint32_t a) {
    asm volatile("ldmatrix.sync.aligned.m8n8.x4.shared.b16 {%0,%1,%2,%3}, [%4];"
                 : "=r"(r[0]), "=r"(r[1]), "=r"(r[2]), "=r"(r[3]) : "r"(a));
}
__device__ __forceinline__ void ldsm_x4t(uint32_t* r, uint32_t a) {
    asm volatile("ldmatrix.sync.aligned.m8n8.x4.trans.shared.b16 {%0,%1,%2,%3}, [%4];"
                 : "=r"(r[0]), "=r"(r[1]), "=r"(r[2]), "=r"(r[3]) : "r"(a));
}
// D(16x8,f32) += A(16x16,f16) * B(16x8,f16)
__device__ __forceinline__ void mma16(float* d, const uint32_t* a, uint32_t b0, uint32_t b1) {
    asm volatile(
        "mma.sync.aligned.m16n8k16.row.col.f32.f16.f16.f32 "
        "{%0,%1,%2,%3}, {%4,%5,%6,%7}, {%8,%9}, {%0,%1,%2,%3};"
        : "+f"(d[0]), "+f"(d[1]), "+f"(d[2]), "+f"(d[3])
        : "r"(a[0]), "r"(a[1]), "r"(a[2]), "r"(a[3]), "r"(b0), "r"(b1));
}
__device__ __forceinline__ uint32_t packh2(float hi, float lo) {
    uint32_t r;
    asm("cvt.rn.f16x2.f32 %0, %1, %2;" : "=r"(r) : "f"(hi), "f"(lo));
    return r;
}
__device__ __forceinline__ uint32_t hfma2u(uint32_t a, uint32_t b, uint32_t c) {
    uint32_t d;
    asm("fma.rn.f16x2 %0, %1, %2, %3;" : "=r"(d) : "r"(a), "r"(b), "r"(c));
    return d;
}
__device__ __forceinline__ uint32_t ex2h2(uint32_t x) {
    uint32_t r;
    asm("ex2.approx.f16x2 %0, %1;" : "=r"(r) : "r"(x));
    return r;
}
__device__ __forceinline__ float2 h22f2(uint32_t h) {
    __half2 hh = *(__half2*)&h;
    return __half22float2(hh);
}

// ---------------- fp32 -> fp16 conversion pre-pass --------------------------
__global__ __launch_bounds__(256) void cvt_x3(
    const float* __restrict__ q, const float* __restrict__ k, const float* __restrict__ v)
{
    const float* src = blockIdx.y == 0 ? q : blockIdx.y == 1 ? k : v;
    __half* dst = g_hx[blockIdx.y];
    size_t i = ((size_t)blockIdx.x * 256 + threadIdx.x) * 4;
    float4 f = *(const float4*)(src + i);
    __half2* d = (__half2*)(dst + i);
    d[0] = __floats2half2_rn(f.x, f.y);
    d[1] = __floats2half2_rn(f.z, f.w);
}
__global__ __launch_bounds__(256) void cvt_w4(
    const float* __restrict__ w0, const float* __restrict__ w1,
    const float* __restrict__ w2, const float* __restrict__ w3)
{
    const float* src = blockIdx.y == 0 ? w0 : blockIdx.y == 1 ? w1
                     : blockIdx.y == 2 ? w2 : w3;
    __half* dst = g_hw[blockIdx.y];
    size_t i = ((size_t)blockIdx.x * 256 + threadIdx.x) * 4;
    float4 f = *(const float4*)(src + i);
    __half2* d = (__half2*)(dst + i);
    d[0] = __floats2half2_rn(f.x, f.y);
    d[1] = __floats2half2_rn(f.z, f.w);
}

// ============ fp16 GEMM core: 128x128 tile, 8 warps, 3-stage cp.async ======
#define GA_ST 5120      // halves per A stage (128 x 40)
#define GB_ST 4352      // halves per B stage (32 x 136)
#define G_SMEM ((3 * GA_ST + 3 * GB_ST) * 2)

template <typename EpiFn>
__device__ __forceinline__ void gemm_body16(
    const __half* __restrict__ X, const __half* __restrict__ W,
    int m0, int n0, EpiFn epi)
{
    extern __shared__ __half gsm[];
    __half* As = gsm;
    __half* Bs = gsm + 3 * GA_ST;
    const uint32_t aB = smem_u32(As);
    const uint32_t bB = smem_u32(Bs);
    const int tid = threadIdx.x;
    const int lane = tid & 31, wid = tid >> 5;
    const int g = lane >> 2, t = lane & 3;
    const int mbase = (wid & 3) * 32, nbase = (wid >> 2) * 64;

    float acc[2][8][4];
#pragma unroll
    for (int mt = 0; mt < 2; mt++)
#pragma unroll
        for (int nt = 0; nt < 8; nt++)
#pragma unroll
            for (int u = 0; u < 4; u++) acc[mt][nt][u] = 0.f;

    auto issue = [&](int kt, int st) {
#pragma unroll
        for (int i = 0; i < 2; i++) {
            int idx = tid + 256 * i;
            int row = idx >> 2, off = (idx & 3) * 8;
            cp16(aB + (uint32_t)((st * GA_ST + row * 40 + off) * 2),
                 X + (size_t)(m0 + row) * DM + kt * 32 + off);
            int kr = idx >> 4, noff = (idx & 15) * 8;
            cp16(bB + (uint32_t)((st * GB_ST + kr * 136 + noff) * 2),
                 W + (size_t)(kt * 32 + kr) * DM + n0 + noff);
        }
        CP_COMMIT();
    };

    const int arow = (lane & 15);
    const int acol = ((lane >> 4) << 3);
    const int bk   = (lane & 15);
    const int bn   = ((lane >> 4) << 3);

    issue(0, 0);
    issue(1, 1);
    for (int kt = 0; kt < 32; kt++) {
        const int st = kt - (kt / 3) * 3;
        __syncthreads();
        if (kt + 2 < 32) issue(kt + 2, (kt + 2) % 3);
        else CP_COMMIT();
        CP_WAIT(2);
        __syncthreads();

        uint32_t a[2][2][4];
#pragma unroll
        for (int mt = 0; mt < 2; mt++)
#pragma unroll
            for (int kh = 0; kh < 2; kh++)
                ldsm_x4(a[mt][kh],
                        aB + (uint32_t)((st * GA_ST
                              + (mbase + mt * 16 + arow) * 40
                              + kh * 16 + acol) * 2));
#pragma unroll
        for (int kh = 0; kh < 2; kh++) {
#pragma unroll
            for (int p = 0; p < 4; p++) {
                uint32_t bf[4];
                ldsm_x4t(bf, bB + (uint32_t)((st * GB_ST
                                  + (kh * 16 + bk) * 136
                                  + nbase + p * 16 + bn) * 2));
                mma16(acc[0][2 * p],     a[0][kh], bf[0], bf[1]);
                mma16(acc[0][2 * p + 1], a[0][kh], bf[2], bf[3]);
                mma16(acc[1][2 * p],     a[1][kh], bf[0], bf[1]);
                mma16(acc[1][2 * p + 1], a[1][kh], bf[2], bf[3]);
            }
        }
    }
    epi(acc, mbase, nbase, g, t);
}

// ---------------- fused Q/K/V projection GEMM ------------------------------
__global__ __launch_bounds__(256, 2) void proj_gemm_tc(
    const float* __restrict__ Bq, const float* __restrict__ Bk, const float* __restrict__ Bv)
{
    const __half* X = g_hx[blockIdx.z];
    const __half* W = g_hw[blockIdx.z];
    const float* Bi = blockIdx.z == 0 ? Bq : blockIdx.z == 1 ? Bk : Bv;
    __half* Out = blockIdx.z == 0 ? g_q : blockIdx.z == 1 ? g_k : g_v;
    const float scale = blockIdx.z == 0 ? 0.125f : 1.0f;
    const int m0 = blockIdx.y * 128, n0 = blockIdx.x * 128;

    gemm_body16(X, W, m0, n0,
        [&](float acc[2][8][4], int mbase, int nbase, int g, int t) {
#pragma unroll
            for (int mt = 0; mt < 2; mt++) {
#pragma unroll
                for (int rr = 0; rr < 2; rr++) {
                    int m = m0 + mbase + mt * 16 + g + 8 * rr;
                    int bb = m >> 11, t_ = m & (TLEN - 1);
#pragma unroll
                    for (int nt = 0; nt < 8; nt++) {
                        int n = n0 + nbase + nt * 8 + 2 * t;
                        int h = n >> 6, d = n & 63;
                        float v0 = (acc[mt][nt][rr * 2 + 0] + Bi[n]) * scale;
                        float v1 = (acc[mt][nt][rr * 2 + 1] + Bi[n + 1]) * scale;
                        __half2* dst = (__half2*)(Out
                            + (((size_t)(bb * NH + h)) * TLEN + t_) * DK + d);
                        *dst = __floats2half2_rn(v0, v1);
                    }
                }
            }
        });
}

// ---------------- output projection GEMM (writes fp32 result) --------------
__global__ __launch_bounds__(256, 2) void out_gemm_tc(
    const float* __restrict__ Bi, float* __restrict__ Out)
{
    const int m0 = blockIdx.y * 128, n0 = blockIdx.x * 128;
    gemm_body16(g_x, g_hw[3], m0, n0,
        [&](float acc[2][8][4], int mbase, int nbase, int g, int t) {
#pragma unroll
            for (int mt = 0; mt < 2; mt++) {
#pragma unroll
                for (int rr = 0; rr < 2; rr++) {
                    int m = m0 + mbase + mt * 16 + g + 8 * rr;
#pragma unroll
                    for (int nt = 0; nt < 8; nt++) {
                        int n = n0 + nbase + nt * 8 + 2 * t;
                        float2 v;
                        v.x = acc[mt][nt][rr * 2 + 0] + Bi[n];
                        v.y = acc[mt][nt][rr * 2 + 1] + Bi[n + 1];
                        *(float2*)(Out + (size_t)m * DM + n) = v;
                    }
                }
            }
        });
}

// =============== fp16 HMMA flash attention with relative positions =========
// Br=128 (8 warps x 16 rows), Bc=64. K dbl-buffered, V single-buffered with
// late wait; f16x2 ex2 softmax on tail blocks, exact fp32 near diagonal.
#define AT_Q    0                     // 128 x 72 halves
#define AT_K    18432                 // 2 x 64 x 72 halves
#define AT_V    36864                 // 64 x 72 halves
#define AT_TBL  46080                 // 32 x 72 halves (rpr_key, rows 17.. zeroed)
#define AT_QR   50688                 // 128 x 17 f32 (scaled by L2E)
#define AT_RVT  59392                 // 17 x 64 f32
#define AT_SI   63744                 // 128 x 17 f32
#define AT_SMEM_BYTES 72448
#define NIT (TLEN / 64)

__global__ __launch_bounds__(256, 2) void flash_attn_tc(
    const float* __restrict__ tabk, const float* __restrict__ rvt_g)
{
    extern __shared__ char sm8[];
    const uint32_t qB = smem_u32(sm8) + AT_Q;
    const uint32_t kB = smem_u32(sm8) + AT_K;
    const uint32_t vB = smem_u32(sm8) + AT_V;
    const uint32_t tB = smem_u32(sm8) + AT_TBL;
    float* qrs  = (float*)(sm8 + AT_QR);
    float* rvts = (float*)(sm8 + AT_RVT);
    float* sInt = (float*)(sm8 + AT_SI);

    const int tid = threadIdx.x;
    const int wid = tid >> 5, lane = tid & 31;
    const int g = lane >> 2, t = lane & 3;
    const int b = blockIdx.z, h = blockIdx.y;
    const int i0 = blockIdx.x * 128;
    const size_t bh = (size_t)(b * NH + h) * TLEN;

    const int r0 = wid * 16 + g;
    const int r1 = r0 + 8;
    const int gi0 = i0 + r0, gi1 = i0 + r1;

    const __half* kgl = g_k + bh * DK;
    const __half* vgl = g_v + bh * DK;

    auto issueK = [&](int it, int st) {
        const __half* kp = kgl + (size_t)(it * 64) * DK;
#pragma unroll
        for (int i = 0; i < 2; i++) {
            int idx = tid + 256 * i;
            int row = idx >> 3, off = (idx & 7) * 8;
            cp16(kB + (uint32_t)((st * 4608 + row * 72 + off) * 2), kp + row * 64 + off);
        }
        CP_COMMIT();
    };
    auto issueV = [&](int it) {
        const __half* vp = vgl + (size_t)(it * 64) * DK;
#pragma unroll
        for (int i = 0; i < 2; i++) {
            int idx = tid + 256 * i;
            int row = idx >> 3, off = (idx & 7) * 8;
            cp16(vB + (uint32_t)((row * 72 + off) * 2), vp + row * 64 + off);
        }
        CP_COMMIT();
    };

    // prologue: Q group, K0 group; scalar tables
    {
        const __half* qp = g_q + (bh + i0) * DK;
#pragma unroll
        for (int i = 0; i < 4; i++) {
            int idx = tid + 256 * i;
            int row = idx >> 3, off = (idx & 7) * 8;
            cp16(qB + (uint32_t)((row * 72 + off) * 2), qp + row * 64 + off);
        }
        CP_COMMIT();
    }
    issueK(0, 0);
    {
        for (int idx = tid; idx < 15 * 32; idx += 256) {
            int r = 17 + idx / 32, c = (idx & 31);
            *(uint32_t*)(sm8 + AT_TBL + ((size_t)r * 72 + c * 2) * 2) = 0u;
        }
        for (int idx = tid; idx < 17 * 32; idx += 256) {
            int r = idx / 32, c2 = (idx & 31) * 2;
            float2 f = *(const float2*)(tabk + r * 64 + c2);
            *(__half2*)(sm8 + AT_TBL + ((size_t)r * 72 + c2) * 2) = __floats2half2_rn(f.x, f.y);
        }
        for (int idx = tid; idx < NR * 64; idx += 256)  rvts[idx] = rvt_g[idx];
        for (int idx = tid; idx < 128 * 17; idx += 256) sInt[idx] = 0.f;
    }
    CP_WAIT(1);            // Q arrived (K0 may still be in flight)
    __syncthreads();       // Q + table visible

    const int qrow = wid * 16 + (lane & 15);
    const int qcol = ((lane >> 4) << 3);
    const int skey = ((lane >> 4) << 3) + (lane & 7);
    const int sd   = (lane & 8);
    const int vkey = (lane & 15);
    const int vd   = ((lane >> 4) << 3);

    uint32_t qa[4][4];
#pragma unroll
    for (int kh = 0; kh < 4; kh++)
        ldsm_x4(qa[kh], qB + (uint32_t)((qrow * 72 + kh * 16 + qcol) * 2));

    // qr = Q @ table^T  (n padded to 32; cols >=17 ignored)
    {
        float qracc[4][4];
#pragma unroll
        for (int p = 0; p < 4; p++)
#pragma unroll
            for (int u = 0; u < 4; u++) qracc[p][u] = 0.f;
#pragma unroll
        for (int kh = 0; kh < 4; kh++) {
#pragma unroll
            for (int p = 0; p < 2; p++) {
                uint32_t tf[4];
                ldsm_x4(tf, tB + (uint32_t)(((p * 16 + skey) * 72 + kh * 16 + sd) * 2));
                mma16(qracc[2 * p],     qa[kh], tf[0], tf[1]);
                mma16(qracc[2 * p + 1], qa[kh], tf[2], tf[3]);
            }
        }
#pragma unroll
        for (int p2 = 0; p2 < 3; p2++) {
#pragma unroll
            for (int cc = 0; cc < 2; cc++) {
                int e = p2 * 8 + 2 * t + cc;
                if (e < 17) {
                    qrs[r0 * 17 + e] = qracc[p2][cc] * L2E;
                    qrs[r1 * 17 + e] = qracc[p2][2 + cc] * L2E;
                }
            }
        }
    }
    __syncthreads();
    const float qt0_0  = qrs[r0 * 17 + 0],  qt16_0 = qrs[r0 * 17 + 16];
    const float qt0_1  = qrs[r1 * 17 + 0],  qt16_1 = qrs[r1 * 17 + 16];
    const uint32_t l2e2   = packh2(L2E, L2E);
    const uint32_t qt0h_0  = packh2(qt0_0,  qt0_0);
    const uint32_t qt16h_0 = packh2(qt16_0, qt16_0);
    const uint32_t qt0h_1  = packh2(qt0_1,  qt0_1);
    const uint32_t qt16h_1 = packh2(qt16_1, qt16_1);

    float oacc[8][4];
#pragma unroll
    for (int nt = 0; nt < 8; nt++)
#pragma unroll
        for (int u = 0; u < 4; u++) oacc[nt][u] = 0.f;
    float lsum0 = 0.f, lsum1 = 0.f;
    float b0s0 = 0.f, b0s1 = 0.f, b16s0 = 0.f, b16s1 = 0.f;

    for (int it = 0; it < NIT; it++) {
        const int j0 = it * 64;
        __syncthreads();                 // V buffer + K stage reuse safe
        issueV(it);
        if (it + 1 < NIT) { issueK(it + 1, (it + 1) & 1); CP_WAIT(2); }
        else              { CP_WAIT(1); }
        __syncthreads();                 // K(it) ready

        const uint32_t kS = kB + (uint32_t)((it & 1) * 4608 * 2);

        // S = Q @ K^T
        float sacc[8][4];
#pragma unroll
        for (int nt = 0; nt < 8; nt++)
#pragma unroll
            for (int u = 0; u < 4; u++) sacc[nt][u] = 0.f;
#pragma unroll
        for (int kh = 0; kh < 4; kh++) {
#pragma unroll
            for (int p = 0; p < 4; p++) {
                uint32_t bf[4];
                ldsm_x4(bf, kS + (uint32_t)(((p * 16 + skey) * 72
                                 + kh * 16 + sd) * 2));
                mma16(sacc[2 * p],     qa[kh], bf[0], bf[1]);
                mma16(sacc[2 * p + 1], qa[kh], bf[2], bf[3]);
            }
        }

        // softmax; f16x2 ex2 on tail blocks, exact fp32 near diagonal
        uint32_t ep[8][2];
        // ---- row 0
        if (j0 + 71 <= gi0 || j0 >= gi0 + 8) {
            const bool left = (j0 + 71 <= gi0);
            const uint32_t qth = left ? qt0h_0 : qt16h_0;
            float bs = 0.f;
#pragma unroll
            for (int nt = 0; nt < 8; nt++) {
                uint32_t ph = packh2(sacc[nt][1], sacc[nt][0]);
                uint32_t pe = ex2h2(hfma2u(ph, l2e2, qth));
                ep[nt][0] = pe;
                float2 pf = h22f2(pe);
                bs += pf.x + pf.y;
            }
            lsum0 += bs;
            if (left) b0s0 += bs; else b16s0 += bs;
        } else {
#pragma unroll
            for (int nt = 0; nt < 8; nt++) {
                float pv[2];
#pragma unroll
                for (int cc = 0; cc < 2; cc++) {
                    const int j = j0 + nt * 8 + 2 * t + cc;
                    int dd = j - gi0;
                    float add = (dd <= -8) ? qt0_0 : (dd >= 8) ? qt16_0
                                : qrs[r0 * 17 + dd + 8];
                    float p = exp2f(fmaf(sacc[nt][cc], L2E, add));
                    lsum0 += p;
                    if (dd <= -8)      b0s0 += p;
                    else if (dd >= 8)  b16s0 += p;
                    else               sInt[r0 * 17 + dd + 7] = p;
                    pv[cc] = p;
                }
                ep[nt][0] = packh2(pv[1], pv[0]);
            }
        }
        // ---- row 1
        if (j0 + 71 <= gi1 || j0 >= gi1 + 8) {
            const bool left = (j0 + 71 <= gi1);
            const uint32_t qth = left ? qt0h_1 : qt16h_1;
            float bs = 0.f;
#pragma unroll
            for (int nt = 0; nt < 8; nt++) {
                uint32_t ph = packh2(sacc[nt][3], sacc[nt][2]);
                uint32_t pe = ex2h2(hfma2u(ph, l2e2, qth));
                ep[nt][1] = pe;
                float2 pf = h22f2(pe);
                bs += pf.x + pf.y;
            }
            lsum1 += bs;
            if (left) b0s1 += bs; else b16s1 += bs;
        } else {
#pragma unroll
            for (int nt = 0; nt < 8; nt++) {
                float pv[2];
#pragma unroll
                for (int cc = 0; cc < 2; cc++) {
                    const int j = j0 + nt * 8 + 2 * t + cc;
                    int dd = j - gi1;
                    float add = (dd <= -8) ? qt0_1 : (dd >= 8) ? qt16_1
                                : qrs[r1 * 17 + dd + 8];
                    float p = exp2f(fmaf(sacc[nt][2 + cc], L2E, add));
                    lsum1 += p;
                    if (dd <= -8)      b0s1 += p;
                    else if (dd >= 8)  b16s1 += p;
                    else               sInt[r1 * 17 + dd + 7] = p;
                    pv[cc] = p;
                }
                ep[nt][1] = packh2(pv[1], pv[0]);
            }
        }

        if (it + 1 < NIT) CP_WAIT(1); else CP_WAIT(0);
        __syncthreads();                 // V(it) ready

        // O += P @ V  (ep pairs ARE the A-fragments)
#pragma unroll
        for (int ks = 0; ks < 4; ks++) {
            uint32_t pa[4];
            pa[0] = ep[2 * ks][0];
            pa[1] = ep[2 * ks][1];
            pa[2] = ep[2 * ks + 1][0];
            pa[3] = ep[2 * ks + 1][1];
#pragma unroll
            for (int p = 0; p < 4; p++) {
                uint32_t bf[4];
                ldsm_x4t(bf, vB + (uint32_t)(((ks * 16 + vkey) * 72
                                  + p * 16 + vd) * 2));
                mma16(oacc[2 * p],     pa, bf[0], bf[1]);
                mma16(oacc[2 * p + 1], pa, bf[2], bf[3]);
            }
        }
    }

    __syncthreads();
#pragma unroll
    for (int o = 1; o <= 2; o <<= 1) {
        lsum0 += __shfl_xor_sync(0xffffffffu, lsum0, o);
        lsum1 += __shfl_xor_sync(0xffffffffu, lsum1, o);
        b0s0  += __shfl_xor_sync(0xffffffffu, b0s0, o);
        b0s1  += __shfl_xor_sync(0xffffffffu, b0s1, o);
        b16s0 += __shfl_xor_sync(0xffffffffu, b16s0, o);
        b16s1 += __shfl_xor_sync(0xffffffffu, b16s1, o);
    }
    const float linv0 = 1.0f / lsum0, linv1 = 1.0f / lsum1;

    float si0[15], si1[15];
#pragma unroll
    for (int e = 0; e < 15; e++) {
        si0[e] = sInt[r0 * 17 + e];
        si1[e] = sInt[r1 * 17 + e];
    }

    __half* op0 = g_x + ((size_t)(b * TLEN) + gi0) * DM + h * DK;
    __half* op1 = g_x + ((size_t)(b * TLEN) + gi1) * DM + h * DK;
#pragma unroll
    for (int nt = 0; nt < 8; nt++) {
        const int d = nt * 8 + 2 * t;
        float e0a = b0s0 * rvts[d]     + b16s0 * rvts[16 * 64 + d];
        float e0b = b0s0 * rvts[d + 1] + b16s0 * rvts[16 * 64 + d + 1];
        float e1a = b0s1 * rvts[d]     + b16s1 * rvts[16 * 64 + d];
        float e1b = b0s1 * rvts[d + 1] + b16s1 * rvts[16 * 64 + d + 1];
#pragma unroll
        for (int e = 1; e <= 15; e++) {
            float rva = rvts[e * 64 + d], rvb = rvts[e * 64 + d + 1];
            e0a += si0[e - 1] * rva;  e0b += si0[e - 1] * rvb;
            e1a += si1[e - 1] * rva;  e1b += si1[e - 1] * rvb;
        }
        *(__half2*)(op0 + d) = __floats2half2_rn(
            (oacc[nt][0] + e0a) * linv0, (oacc[nt][1] + e0b) * linv0);
        *(__half2*)(op1 + d) = __floats2half2_rn(
            (oacc[nt][2] + e1a) * linv1, (oacc[nt][3] + e1b) * linv1);
    }
}

// ---------------- launch ----------------------------------------------------
extern "C" void kernel_launch(void* const* d_in, const int* in_sizes, int n_in,
                              void* d_out, int out_size)
{
    const float* query = (const float*)d_in[0];
    const float* key_  = (const float*)d_in[1];
    const float* value = (const float*)d_in[2];
    const float* w_q = (const float*)d_in[4];
    const float* b_q = (const float*)d_in[5];
    const float* w_k = (const float*)d_in[6];
    const float* b_k = (const float*)d_in[7];
    const float* w_v = (const float*)d_in[8];
    const float* b_v = (const float*)d_in[9];
    const float* w_o = (const float*)d_in[10];
    const float* b_o = (const float*)d_in[11];
    const float* rpr_k = (const float*)d_in[12];
    const float* rpr_v = (const float*)d_in[13];
    float* out = (float*)d_out;

    cudaFuncSetAttribute(proj_gemm_tc, cudaFuncAttributeMaxDynamicSharedMemorySize, G_SMEM);
    cudaFuncSetAttribute(out_gemm_tc,  cudaFuncAttributeMaxDynamicSharedMemorySize, G_SMEM);
    cudaFuncSetAttribute(flash_attn_tc, cudaFuncAttributeMaxDynamicSharedMemorySize, AT_SMEM_BYTES);

    cvt_x3<<<dim3((BSZ*TLEN*DM) / 1024, 3), 256>>>(query, key_, value);
    cvt_w4<<<dim3((DM*DM) / 1024, 4), 256>>>(w_q, w_k, w_v, w_o);

    proj_gemm_tc<<<dim3(DM / 128, (BSZ * TLEN) / 128, 3), 256, G_SMEM>>>(b_q, b_k, b_v);

    flash_attn_tc<<<dim3(TLEN / 128, NH, BSZ), 256, AT_SMEM_BYTES>>>(rpr_k, rpr_v);

    out_gemm_tc<<<dim3(DM / 128, (BSZ * TLEN) / 128, 1), 256, G_SMEM>>>(b_o, out);
}

// round 16
// speedup vs baseline: 1.0557x; 1.0143x over previous
#include <cuda_runtime.h>
#include <cuda_fp16.h>
#include <math.h>
#include <stdint.h>

#define BSZ 2
#define TLEN 2048
#define DM 1024
#define NH 16
#define DK 64
#define NR 17
#define L2E 1.4426950408889634f

// ---------------- scratch (device globals; no allocation allowed) ----------
__device__ __align__(128) __half g_hx[3][(size_t)BSZ*TLEN*DM]; // fp16 query/key/value inputs
__device__ __align__(128) __half g_hw[4][DM*DM];               // fp16 w_q,w_k,w_v,w_o
__device__ __align__(128) __half g_q[(size_t)BSZ*NH*TLEN*DK];  // scaled by 1/8
__device__ __align__(128) __half g_k[(size_t)BSZ*NH*TLEN*DK];
__device__ __align__(128) __half g_v[(size_t)BSZ*NH*TLEN*DK];
__device__ __align__(128) __half g_x[(size_t)BSZ*TLEN*DM];     // attention out (fp16)

// ---------------- asm helpers ----------------------------------------------
__device__ __forceinline__ uint32_t smem_u32(const void* p) {
    uint32_t a;
    asm("{ .reg .u64 t; cvta.to.shared.u64 t, %1; cvt.u32.u64 %0, t; }"
        : "=r"(a) : "l"(p));
    return a;
}
__device__ __forceinline__ void cp16(uint32_t dst, const void* src) {
    asm volatile("cp.async.cg.shared.global [%0], [%1], 16;"
                 :: "r"(dst), "l"(src));
}
#define CP_COMMIT() asm volatile("cp.async.commit_group;" ::: "memory")
#define CP_WAIT(n)  asm volatile("cp.async.wait_group %0;" :: "n"(n) : "memory")

__device__ __forceinline__ void ldsm_x4(uint32_t* r, uint32_t a) {
    asm volatile("ldmatrix.sync.aligned.m8n8.x4.shared.b16 {%0,%1,%2,%3}, [%4];"
                 : "=r"(r[0]), "=r"(r[1]), "=r"(r[2]), "=r"(r[3]) : "r"(a));
}
__device__ __forceinline__ void ldsm_x4t(uint32_t* r, uint32_t a) {
    asm volatile("ldmatrix.sync.aligned.m8n8.x4.trans.shared.b16 {%0,%1,%2,%3}, [%4];"
                 : "=r"(r[0]), "=r"(r[1]), "=r"(r[2]), "=r"(r[3]) : "r"(a));
}
// D(16x8,f32) += A(16x16,f16) * B(16x8,f16)
__device__ __forceinline__ void mma16(float* d, const uint32_t* a, uint32_t b0, uint32_t b1) {
    asm volatile(
        "mma.sync.aligned.m16n8k16.row.col.f32.f16.f16.f32 "
        "{%0,%1,%2,%3}, {%4,%5,%6,%7}, {%8,%9}, {%0,%1,%2,%3};"
        : "+f"(d[0]), "+f"(d[1]), "+f"(d[2]), "+f"(d[3])
        : "r"(a[0]), "r"(a[1]), "r"(a[2]), "r"(a[3]), "r"(b0), "r"(b1));
}
__device__ __forceinline__ uint32_t packh2(float hi, float lo) {
    uint32_t r;
    asm("cvt.rn.f16x2.f32 %0, %1, %2;" : "=r"(r) : "f"(hi), "f"(lo));
    return r;
}
__device__ __forceinline__ uint32_t hfma2u(uint32_t a, uint32_t b, uint32_t c) {
    uint32_t d;
    asm("fma.rn.f16x2 %0, %1, %2, %3;" : "=r"(d) : "r"(a), "r"(b), "r"(c));
    return d;
}
__device__ __forceinline__ uint32_t ex2h2(uint32_t x) {
    uint32_t r;
    asm("ex2.approx.f16x2 %0, %1;" : "=r"(r) : "r"(x));
    return r;
}
__device__ __forceinline__ float2 h22f2(uint32_t h) {
    __half2 hh = *(__half2*)&h;
    return __half22float2(hh);
}

// ------ fp32 -> fp16 conversion pre-pass: single flat-grid kernel ----------
// Blocks 0..12287: x tensors (3 x 4096 blocks). Blocks 12288..16383: weights
// (4 x 1024 blocks). No wasted blocks, one launch.
#define CVT_XBLK 4096
#define CVT_WBLK 1024
__global__ __launch_bounds__(256) void cvt_all(
    const float* __restrict__ q, const float* __restrict__ k, const float* __restrict__ v,
    const float* __restrict__ w0, const float* __restrict__ w1,
    const float* __restrict__ w2, const float* __restrict__ w3)
{
    int id = blockIdx.x;
    const float* src;
    __half* dst;
    int off;
    if (id < 3 * CVT_XBLK) {
        int z = id / CVT_XBLK;
        off = id - z * CVT_XBLK;
        src = z == 0 ? q : z == 1 ? k : v;
        dst = g_hx[z];
    } else {
        id -= 3 * CVT_XBLK;
        int z = id / CVT_WBLK;
        off = id - z * CVT_WBLK;
        src = z == 0 ? w0 : z == 1 ? w1 : z == 2 ? w2 : w3;
        dst = g_hw[z];
    }
    size_t i = ((size_t)off * 256 + threadIdx.x) * 4;
    float4 f = *(const float4*)(src + i);
    __half2* d = (__half2*)(dst + i);
    d[0] = __floats2half2_rn(f.x, f.y);
    d[1] = __floats2half2_rn(f.z, f.w);
}

// ============ fp16 GEMM core: 128x128 tile, 8 warps, 3-stage cp.async ======
#define GA_ST 5120      // halves per A stage (128 x 40)
#define GB_ST 4352      // halves per B stage (32 x 136)
#define G_SMEM ((3 * GA_ST + 3 * GB_ST) * 2)

template <typename EpiFn>
__device__ __forceinline__ void gemm_body16(
    const __half* __restrict__ X, const __half* __restrict__ W,
    int m0, int n0, EpiFn epi)
{
    extern __shared__ __half gsm[];
    __half* As = gsm;
    __half* Bs = gsm + 3 * GA_ST;
    const uint32_t aB = smem_u32(As);
    const uint32_t bB = smem_u32(Bs);
    const int tid = threadIdx.x;
    const int lane = tid & 31, wid = tid >> 5;
    const int g = lane >> 2, t = lane & 3;
    const int mbase = (wid & 3) * 32, nbase = (wid >> 2) * 64;

    float acc[2][8][4];
#pragma unroll
    for (int mt = 0; mt < 2; mt++)
#pragma unroll
        for (int nt = 0; nt < 8; nt++)
#pragma unroll
            for (int u = 0; u < 4; u++) acc[mt][nt][u] = 0.f;

    auto issue = [&](int kt, int st) {
#pragma unroll
        for (int i = 0; i < 2; i++) {
            int idx = tid + 256 * i;
            int row = idx >> 2, off = (idx & 3) * 8;
            cp16(aB + (uint32_t)((st * GA_ST + row * 40 + off) * 2),
                 X + (size_t)(m0 + row) * DM + kt * 32 + off);
            int kr = idx >> 4, noff = (idx & 15) * 8;
            cp16(bB + (uint32_t)((st * GB_ST + kr * 136 + noff) * 2),
                 W + (size_t)(kt * 32 + kr) * DM + n0 + noff);
        }
        CP_COMMIT();
    };

    const int arow = (lane & 15);
    const int acol = ((lane >> 4) << 3);
    const int bk   = (lane & 15);
    const int bn   = ((lane >> 4) << 3);

    issue(0, 0);
    issue(1, 1);
    for (int kt = 0; kt < 32; kt++) {
        const int st = kt - (kt / 3) * 3;
        __syncthreads();
        if (kt + 2 < 32) issue(kt + 2, (kt + 2) % 3);
        else CP_COMMIT();
        CP_WAIT(2);
        __syncthreads();

        uint32_t a[2][2][4];
#pragma unroll
        for (int mt = 0; mt < 2; mt++)
#pragma unroll
            for (int kh = 0; kh < 2; kh++)
                ldsm_x4(a[mt][kh],
                        aB + (uint32_t)((st * GA_ST
                              + (mbase + mt * 16 + arow) * 40
                              + kh * 16 + acol) * 2));
#pragma unroll
        for (int kh = 0; kh < 2; kh++) {
#pragma unroll
            for (int p = 0; p < 4; p++) {
                uint32_t bf[4];
                ldsm_x4t(bf, bB + (uint32_t)((st * GB_ST
                                  + (kh * 16 + bk) * 136
                                  + nbase + p * 16 + bn) * 2));
                mma16(acc[0][2 * p],     a[0][kh], bf[0], bf[1]);
                mma16(acc[0][2 * p + 1], a[0][kh], bf[2], bf[3]);
                mma16(acc[1][2 * p],     a[1][kh], bf[0], bf[1]);
                mma16(acc[1][2 * p + 1], a[1][kh], bf[2], bf[3]);
            }
        }
    }
    epi(acc, mbase, nbase, g, t);
}

// ---------------- fused Q/K/V projection GEMM ------------------------------
__global__ __launch_bounds__(256, 2) void proj_gemm_tc(
    const float* __restrict__ Bq, const float* __restrict__ Bk, const float* __restrict__ Bv)
{
    const __half* X = g_hx[blockIdx.z];
    const __half* W = g_hw[blockIdx.z];
    const float* Bi = blockIdx.z == 0 ? Bq : blockIdx.z == 1 ? Bk : Bv;
    __half* Out = blockIdx.z == 0 ? g_q : blockIdx.z == 1 ? g_k : g_v;
    const float scale = blockIdx.z == 0 ? 0.125f : 1.0f;
    const int m0 = blockIdx.y * 128, n0 = blockIdx.x * 128;

    gemm_body16(X, W, m0, n0,
        [&](float acc[2][8][4], int mbase, int nbase, int g, int t) {
#pragma unroll
            for (int mt = 0; mt < 2; mt++) {
#pragma unroll
                for (int rr = 0; rr < 2; rr++) {
                    int m = m0 + mbase + mt * 16 + g + 8 * rr;
                    int bb = m >> 11, t_ = m & (TLEN - 1);
#pragma unroll
                    for (int nt = 0; nt < 8; nt++) {
                        int n = n0 + nbase + nt * 8 + 2 * t;
                        int h = n >> 6, d = n & 63;
                        float v0 = (acc[mt][nt][rr * 2 + 0] + Bi[n]) * scale;
                        float v1 = (acc[mt][nt][rr * 2 + 1] + Bi[n + 1]) * scale;
                        __half2* dst = (__half2*)(Out
                            + (((size_t)(bb * NH + h)) * TLEN + t_) * DK + d);
                        *dst = __floats2half2_rn(v0, v1);
                    }
                }
            }
        });
}

// ---------------- output projection GEMM (writes fp32 result) --------------
__global__ __launch_bounds__(256, 2) void out_gemm_tc(
    const float* __restrict__ Bi, float* __restrict__ Out)
{
    const int m0 = blockIdx.y * 128, n0 = blockIdx.x * 128;
    gemm_body16(g_x, g_hw[3], m0, n0,
        [&](float acc[2][8][4], int mbase, int nbase, int g, int t) {
#pragma unroll
            for (int mt = 0; mt < 2; mt++) {
#pragma unroll
                for (int rr = 0; rr < 2; rr++) {
                    int m = m0 + mbase + mt * 16 + g + 8 * rr;
#pragma unroll
                    for (int nt = 0; nt < 8; nt++) {
                        int n = n0 + nbase + nt * 8 + 2 * t;
                        float2 v;
                        v.x = acc[mt][nt][rr * 2 + 0] + Bi[n];
                        v.y = acc[mt][nt][rr * 2 + 1] + Bi[n + 1];
                        *(float2*)(Out + (size_t)m * DM + n) = v;
                    }
                }
            }
        });
}

// =============== fp16 HMMA flash attention with relative positions =========
// Br=128 (8 warps x 16 rows), Bc=64. K dbl-buffered, V single-buffered with
// late wait; f16x2 ex2 softmax on tail blocks, exact fp32 near diagonal.
#define AT_Q    0                     // 128 x 72 halves
#define AT_K    18432                 // 2 x 64 x 72 halves
#define AT_V    36864                 // 64 x 72 halves
#define AT_TBL  46080                 // 32 x 72 halves (rpr_key, rows 17.. zeroed)
#define AT_QR   50688                 // 128 x 17 f32 (scaled by L2E)
#define AT_RVT  59392                 // 17 x 64 f32
#define AT_SI   63744                 // 128 x 17 f32
#define AT_SMEM_BYTES 72448
#define NIT (TLEN / 64)

__global__ __launch_bounds__(256, 2) void flash_attn_tc(
    const float* __restrict__ tabk, const float* __restrict__ rvt_g)
{
    extern __shared__ char sm8[];
    const uint32_t qB = smem_u32(sm8) + AT_Q;
    const uint32_t kB = smem_u32(sm8) + AT_K;
    const uint32_t vB = smem_u32(sm8) + AT_V;
    const uint32_t tB = smem_u32(sm8) + AT_TBL;
    float* qrs  = (float*)(sm8 + AT_QR);
    float* rvts = (float*)(sm8 + AT_RVT);
    float* sInt = (float*)(sm8 + AT_SI);

    const int tid = threadIdx.x;
    const int wid = tid >> 5, lane = tid & 31;
    const int g = lane >> 2, t = lane & 3;
    const int b = blockIdx.z, h = blockIdx.y;
    const int i0 = blockIdx.x * 128;
    const size_t bh = (size_t)(b * NH + h) * TLEN;

    const int r0 = wid * 16 + g;
    const int r1 = r0 + 8;
    const int gi0 = i0 + r0, gi1 = i0 + r1;

    const __half* kgl = g_k + bh * DK;
    const __half* vgl = g_v + bh * DK;

    auto issueK = [&](int it, int st) {
        const __half* kp = kgl + (size_t)(it * 64) * DK;
#pragma unroll
        for (int i = 0; i < 2; i++) {
            int idx = tid + 256 * i;
            int row = idx >> 3, off = (idx & 7) * 8;
            cp16(kB + (uint32_t)((st * 4608 + row * 72 + off) * 2), kp + row * 64 + off);
        }
        CP_COMMIT();
    };
    auto issueV = [&](int it) {
        const __half* vp = vgl + (size_t)(it * 64) * DK;
#pragma unroll
        for (int i = 0; i < 2; i++) {
            int idx = tid + 256 * i;
            int row = idx >> 3, off = (idx & 7) * 8;
            cp16(vB + (uint32_t)((row * 72 + off) * 2), vp + row * 64 + off);
        }
        CP_COMMIT();
    };

    // prologue: Q group, K0 group; scalar tables
    {
        const __half* qp = g_q + (bh + i0) * DK;
#pragma unroll
        for (int i = 0; i < 4; i++) {
            int idx = tid + 256 * i;
            int row = idx >> 3, off = (idx & 7) * 8;
            cp16(qB + (uint32_t)((row * 72 + off) * 2), qp + row * 64 + off);
        }
        CP_COMMIT();
    }
    issueK(0, 0);
    {
        for (int idx = tid; idx < 15 * 32; idx += 256) {
            int r = 17 + idx / 32, c = (idx & 31);
            *(uint32_t*)(sm8 + AT_TBL + ((size_t)r * 72 + c * 2) * 2) = 0u;
        }
        for (int idx = tid; idx < 17 * 32; idx += 256) {
            int r = idx / 32, c2 = (idx & 31) * 2;
            float2 f = *(const float2*)(tabk + r * 64 + c2);
            *(__half2*)(sm8 + AT_TBL + ((size_t)r * 72 + c2) * 2) = __floats2half2_rn(f.x, f.y);
        }
        for (int idx = tid; idx < NR * 64; idx += 256)  rvts[idx] = rvt_g[idx];
        for (int idx = tid; idx < 128 * 17; idx += 256) sInt[idx] = 0.f;
    }
    CP_WAIT(1);            // Q arrived (K0 may still be in flight)
    __syncthreads();       // Q + table visible

    const int qrow = wid * 16 + (lane & 15);
    const int qcol = ((lane >> 4) << 3);
    const int skey = ((lane >> 4) << 3) + (lane & 7);
    const int sd   = (lane & 8);
    const int vkey = (lane & 15);
    const int vd   = ((lane >> 4) << 3);

    uint32_t qa[4][4];
#pragma unroll
    for (int kh = 0; kh < 4; kh++)
        ldsm_x4(qa[kh], qB + (uint32_t)((qrow * 72 + kh * 16 + qcol) * 2));

    // qr = Q @ table^T  (n padded to 32; cols >=17 ignored)
    {
        float qracc[4][4];
#pragma unroll
        for (int p = 0; p < 4; p++)
#pragma unroll
            for (int u = 0; u < 4; u++) qracc[p][u] = 0.f;
#pragma unroll
        for (int kh = 0; kh < 4; kh++) {
#pragma unroll
            for (int p = 0; p < 2; p++) {
                uint32_t tf[4];
                ldsm_x4(tf, tB + (uint32_t)(((p * 16 + skey) * 72 + kh * 16 + sd) * 2));
                mma16(qracc[2 * p],     qa[kh], tf[0], tf[1]);
                mma16(qracc[2 * p + 1], qa[kh], tf[2], tf[3]);
            }
        }
#pragma unroll
        for (int p2 = 0; p2 < 3; p2++) {
#pragma unroll
            for (int cc = 0; cc < 2; cc++) {
                int e = p2 * 8 + 2 * t + cc;
                if (e < 17) {
                    qrs[r0 * 17 + e] = qracc[p2][cc] * L2E;
                    qrs[r1 * 17 + e] = qracc[p2][2 + cc] * L2E;
                }
            }
        }
    }
    __syncthreads();
    const float qt0_0  = qrs[r0 * 17 + 0],  qt16_0 = qrs[r0 * 17 + 16];
    const float qt0_1  = qrs[r1 * 17 + 0],  qt16_1 = qrs[r1 * 17 + 16];
    const uint32_t l2e2   = packh2(L2E, L2E);
    const uint32_t qt0h_0  = packh2(qt0_0,  qt0_0);
    const uint32_t qt16h_0 = packh2(qt16_0, qt16_0);
    const uint32_t qt0h_1  = packh2(qt0_1,  qt0_1);
    const uint32_t qt16h_1 = packh2(qt16_1, qt16_1);

    float oacc[8][4];
#pragma unroll
    for (int nt = 0; nt < 8; nt++)
#pragma unroll
        for (int u = 0; u < 4; u++) oacc[nt][u] = 0.f;
    float lsum0 = 0.f, lsum1 = 0.f;
    float b0s0 = 0.f, b0s1 = 0.f, b16s0 = 0.f, b16s1 = 0.f;

    for (int it = 0; it < NIT; it++) {
        const int j0 = it * 64;
        __syncthreads();                 // V buffer + K stage reuse safe
        issueV(it);
        if (it + 1 < NIT) { issueK(it + 1, (it + 1) & 1); CP_WAIT(2); }
        else              { CP_WAIT(1); }
        __syncthreads();                 // K(it) ready

        const uint32_t kS = kB + (uint32_t)((it & 1) * 4608 * 2);

        // S = Q @ K^T
        float sacc[8][4];
#pragma unroll
        for (int nt = 0; nt < 8; nt++)
#pragma unroll
            for (int u = 0; u < 4; u++) sacc[nt][u] = 0.f;
#pragma unroll
        for (int kh = 0; kh < 4; kh++) {
#pragma unroll
            for (int p = 0; p < 4; p++) {
                uint32_t bf[4];
                ldsm_x4(bf, kS + (uint32_t)(((p * 16 + skey) * 72
                                 + kh * 16 + sd) * 2));
                mma16(sacc[2 * p],     qa[kh], bf[0], bf[1]);
                mma16(sacc[2 * p + 1], qa[kh], bf[2], bf[3]);
            }
        }

        // softmax; f16x2 ex2 on tail blocks, exact fp32 near diagonal
        uint32_t ep[8][2];
        // ---- row 0
        if (j0 + 71 <= gi0 || j0 >= gi0 + 8) {
            const bool left = (j0 + 71 <= gi0);
            const uint32_t qth = left ? qt0h_0 : qt16h_0;
            float bs = 0.f;
#pragma unroll
            for (int nt = 0; nt < 8; nt++) {
                uint32_t ph = packh2(sacc[nt][1], sacc[nt][0]);
                uint32_t pe = ex2h2(hfma2u(ph, l2e2, qth));
                ep[nt][0] = pe;
                float2 pf = h22f2(pe);
                bs += pf.x + pf.y;
            }
            lsum0 += bs;
            if (left) b0s0 += bs; else b16s0 += bs;
        } else {
#pragma unroll
            for (int nt = 0; nt < 8; nt++) {
                float pv[2];
#pragma unroll
                for (int cc = 0; cc < 2; cc++) {
                    const int j = j0 + nt * 8 + 2 * t + cc;
                    int dd = j - gi0;
                    float add = (dd <= -8) ? qt0_0 : (dd >= 8) ? qt16_0
                                : qrs[r0 * 17 + dd + 8];
                    float p = exp2f(fmaf(sacc[nt][cc], L2E, add));
                    lsum0 += p;
                    if (dd <= -8)      b0s0 += p;
                    else if (dd >= 8)  b16s0 += p;
                    else               sInt[r0 * 17 + dd + 7] = p;
                    pv[cc] = p;
                }
                ep[nt][0] = packh2(pv[1], pv[0]);
            }
        }
        // ---- row 1
        if (j0 + 71 <= gi1 || j0 >= gi1 + 8) {
            const bool left = (j0 + 71 <= gi1);
            const uint32_t qth = left ? qt0h_1 : qt16h_1;
            float bs = 0.f;
#pragma unroll
            for (int nt = 0; nt < 8; nt++) {
                uint32_t ph = packh2(sacc[nt][3], sacc[nt][2]);
                uint32_t pe = ex2h2(hfma2u(ph, l2e2, qth));
                ep[nt][1] = pe;
                float2 pf = h22f2(pe);
                bs += pf.x + pf.y;
            }
            lsum1 += bs;
            if (left) b0s1 += bs; else b16s1 += bs;
        } else {
#pragma unroll
            for (int nt = 0; nt < 8; nt++) {
                float pv[2];
#pragma unroll
                for (int cc = 0; cc < 2; cc++) {
                    const int j = j0 + nt * 8 + 2 * t + cc;
                    int dd = j - gi1;
                    float add = (dd <= -8) ? qt0_1 : (dd >= 8) ? qt16_1
                                : qrs[r1 * 17 + dd + 8];
                    float p = exp2f(fmaf(sacc[nt][2 + cc], L2E, add));
                    lsum1 += p;
                    if (dd <= -8)      b0s1 += p;
                    else if (dd >= 8)  b16s1 += p;
                    else               sInt[r1 * 17 + dd + 7] = p;
                    pv[cc] = p;
                }
                ep[nt][1] = packh2(pv[1], pv[0]);
            }
        }

        if (it + 1 < NIT) CP_WAIT(1); else CP_WAIT(0);
        __syncthreads();                 // V(it) ready

        // O += P @ V  (ep pairs ARE the A-fragments)
#pragma unroll
        for (int ks = 0; ks < 4; ks++) {
            uint32_t pa[4];
            pa[0] = ep[2 * ks][0];
            pa[1] = ep[2 * ks][1];
            pa[2] = ep[2 * ks + 1][0];
            pa[3] = ep[2 * ks + 1][1];
#pragma unroll
            for (int p = 0; p < 4; p++) {
                uint32_t bf[4];
                ldsm_x4t(bf, vB + (uint32_t)(((ks * 16 + vkey) * 72
                                  + p * 16 + vd) * 2));
                mma16(oacc[2 * p],     pa, bf[0], bf[1]);
                mma16(oacc[2 * p + 1], pa, bf[2], bf[3]);
            }
        }
    }

    __syncthreads();
#pragma unroll
    for (int o = 1; o <= 2; o <<= 1) {
        lsum0 += __shfl_xor_sync(0xffffffffu, lsum0, o);
        lsum1 += __shfl_xor_sync(0xffffffffu, lsum1, o);
        b0s0  += __shfl_xor_sync(0xffffffffu, b0s0, o);
        b0s1  += __shfl_xor_sync(0xffffffffu, b0s1, o);
        b16s0 += __shfl_xor_sync(0xffffffffu, b16s0, o);
        b16s1 += __shfl_xor_sync(0xffffffffu, b16s1, o);
    }
    const float linv0 = 1.0f / lsum0, linv1 = 1.0f / lsum1;

    float si0[15], si1[15];
#pragma unroll
    for (int e = 0; e < 15; e++) {
        si0[e] = sInt[r0 * 17 + e];
        si1[e] = sInt[r1 * 17 + e];
    }

    __half* op0 = g_x + ((size_t)(b * TLEN) + gi0) * DM + h * DK;
    __half* op1 = g_x + ((size_t)(b * TLEN) + gi1) * DM + h * DK;
#pragma unroll
    for (int nt = 0; nt < 8; nt++) {
        const int d = nt * 8 + 2 * t;
        float e0a = b0s0 * rvts[d]     + b16s0 * rvts[16 * 64 + d];
        float e0b = b0s0 * rvts[d + 1] + b16s0 * rvts[16 * 64 + d + 1];
        float e1a = b0s1 * rvts[d]     + b16s1 * rvts[16 * 64 + d];
        float e1b = b0s1 * rvts[d + 1] + b16s1 * rvts[16 * 64 + d + 1];
#pragma unroll
        for (int e = 1; e <= 15; e++) {
            float rva = rvts[e * 64 + d], rvb = rvts[e * 64 + d + 1];
            e0a += si0[e - 1] * rva;  e0b += si0[e - 1] * rvb;
            e1a += si1[e - 1] * rva;  e1b += si1[e - 1] * rvb;
        }
        *(__half2*)(op0 + d) = __floats2half2_rn(
            (oacc[nt][0] + e0a) * linv0, (oacc[nt][1] + e0b) * linv0);
        *(__half2*)(op1 + d) = __floats2half2_rn(
            (oacc[nt][2] + e1a) * linv1, (oacc[nt][3] + e1b) * linv1);
    }
}

// ---------------- launch ----------------------------------------------------
extern "C" void kernel_launch(void* const* d_in, const int* in_sizes, int n_in,
                              void* d_out, int out_size)
{
    const float* query = (const float*)d_in[0];
    const float* key_  = (const float*)d_in[1];
    const float* value = (const float*)d_in[2];
    const float* w_q = (const float*)d_in[4];
    const float* b_q = (const float*)d_in[5];
    const float* w_k = (const float*)d_in[6];
    const float* b_k = (const float*)d_in[7];
    const float* w_v = (const float*)d_in[8];
    const float* b_v = (const float*)d_in[9];
    const float* w_o = (const float*)d_in[10];
    const float* b_o = (const float*)d_in[11];
    const float* rpr_k = (const float*)d_in[12];
    const float* rpr_v = (const float*)d_in[13];
    float* out = (float*)d_out;

    cudaFuncSetAttribute(proj_gemm_tc, cudaFuncAttributeMaxDynamicSharedMemorySize, G_SMEM);
    cudaFuncSetAttribute(out_gemm_tc,  cudaFuncAttributeMaxDynamicSharedMemorySize, G_SMEM);
    cudaFuncSetAttribute(flash_attn_tc, cudaFuncAttributeMaxDynamicSharedMemorySize, AT_SMEM_BYTES);

    cvt_all<<<3 * CVT_XBLK + 4 * CVT_WBLK, 256>>>(
        query, key_, value, w_q, w_k, w_v, w_o);

    proj_gemm_tc<<<dim3(DM / 128, (BSZ * TLEN) / 128, 3), 256, G_SMEM>>>(b_q, b_k, b_v);

    flash_attn_tc<<<dim3(TLEN / 128, NH, BSZ), 256, AT_SMEM_BYTES>>>(rpr_k, rpr_v);

    out_gemm_tc<<<dim3(DM / 128, (BSZ * TLEN) / 128, 1), 256, G_SMEM>>>(b_o, out);
}

// round 17
// speedup vs baseline: 1.0564x; 1.0007x over previous
#include <cuda_runtime.h>
#include <cuda_fp16.h>
#include <math.h>
#include <stdint.h>

#define BSZ 2
#define TLEN 2048
#define DM 1024
#define NH 16
#define DK 64
#define NR 17
#define L2E 1.4426950408889634f

// ---------------- scratch (device globals; no allocation allowed) ----------
__device__ __align__(128) __half g_hx[3][(size_t)BSZ*TLEN*DM]; // fp16 query/key/value inputs
__device__ __align__(128) __half g_hw[4][DM*DM];               // fp16 w_q,w_k,w_v,w_o
__device__ __align__(128) __half g_q[(size_t)BSZ*NH*TLEN*DK];  // scaled by 1/8
__device__ __align__(128) __half g_k[(size_t)BSZ*NH*TLEN*DK];
__device__ __align__(128) __half g_v[(size_t)BSZ*NH*TLEN*DK];
__device__ __align__(128) __half g_x[(size_t)BSZ*TLEN*DM];     // attention out (fp16)

// ---------------- asm helpers ----------------------------------------------
__device__ __forceinline__ uint32_t smem_u32(const void* p) {
    uint32_t a;
    asm("{ .reg .u64 t; cvta.to.shared.u64 t, %1; cvt.u32.u64 %0, t; }"
        : "=r"(a) : "l"(p));
    return a;
}
__device__ __forceinline__ void cp16(uint32_t dst, const void* src) {
    asm volatile("cp.async.cg.shared.global [%0], [%1], 16;"
                 :: "r"(dst), "l"(src));
}
#define CP_COMMIT() asm volatile("cp.async.commit_group;" ::: "memory")
#define CP_WAIT(n)  asm volatile("cp.async.wait_group %0;" :: "n"(n) : "memory")

__device__ __forceinline__ void ldsm_x4(uint32_t* r, uint32_t a) {
    asm volatile("ldmatrix.sync.aligned.m8n8.x4.shared.b16 {%0,%1,%2,%3}, [%4];"
                 : "=r"(r[0]), "=r"(r[1]), "=r"(r[2]), "=r"(r[3]) : "r"(a));
}
__device__ __forceinline__ void ldsm_x4t(uint32_t* r, uint32_t a) {
    asm volatile("ldmatrix.sync.aligned.m8n8.x4.trans.shared.b16 {%0,%1,%2,%3}, [%4];"
                 : "=r"(r[0]), "=r"(r[1]), "=r"(r[2]), "=r"(r[3]) : "r"(a));
}
// D(16x8,f32) += A(16x16,f16) * B(16x8,f16)
__device__ __forceinline__ void mma16(float* d, const uint32_t* a, uint32_t b0, uint32_t b1) {
    asm volatile(
        "mma.sync.aligned.m16n8k16.row.col.f32.f16.f16.f32 "
        "{%0,%1,%2,%3}, {%4,%5,%6,%7}, {%8,%9}, {%0,%1,%2,%3};"
        : "+f"(d[0]), "+f"(d[1]), "+f"(d[2]), "+f"(d[3])
        : "r"(a[0]), "r"(a[1]), "r"(a[2]), "r"(a[3]), "r"(b0), "r"(b1));
}
__device__ __forceinline__ uint32_t packh2(float hi, float lo) {
    uint32_t r;
    asm("cvt.rn.f16x2.f32 %0, %1, %2;" : "=r"(r) : "f"(hi), "f"(lo));
    return r;
}
__device__ __forceinline__ uint32_t hfma2u(uint32_t a, uint32_t b, uint32_t c) {
    uint32_t d;
    asm("fma.rn.f16x2 %0, %1, %2, %3;" : "=r"(d) : "r"(a), "r"(b), "r"(c));
    return d;
}
__device__ __forceinline__ uint32_t ex2h2(uint32_t x) {
    uint32_t r;
    asm("ex2.approx.f16x2 %0, %1;" : "=r"(r) : "r"(x));
    return r;
}
__device__ __forceinline__ float2 h22f2(uint32_t h) {
    __half2 hh = *(__half2*)&h;
    return __half22float2(hh);
}

// ------ fp32 -> fp16 conversion pre-pass: single flat-grid kernel ----------
#define CVT_XBLK 4096
#define CVT_WBLK 1024
__global__ __launch_bounds__(256) void cvt_all(
    const float* __restrict__ q, const float* __restrict__ k, const float* __restrict__ v,
    const float* __restrict__ w0, const float* __restrict__ w1,
    const float* __restrict__ w2, const float* __restrict__ w3)
{
    int id = blockIdx.x;
    const float* src;
    __half* dst;
    int off;
    if (id < 3 * CVT_XBLK) {
        int z = id / CVT_XBLK;
        off = id - z * CVT_XBLK;
        src = z == 0 ? q : z == 1 ? k : v;
        dst = g_hx[z];
    } else {
        id -= 3 * CVT_XBLK;
        int z = id / CVT_WBLK;
        off = id - z * CVT_WBLK;
        src = z == 0 ? w0 : z == 1 ? w1 : z == 2 ? w2 : w3;
        dst = g_hw[z];
    }
    size_t i = ((size_t)off * 256 + threadIdx.x) * 4;
    float4 f = *(const float4*)(src + i);
    __half2* d = (__half2*)(dst + i);
    d[0] = __floats2half2_rn(f.x, f.y);
    d[1] = __floats2half2_rn(f.z, f.w);
}

// ============ fp16 GEMM core: 128x128 tile, 8 warps, 3-stage cp.async ======
#define GA_ST 5120      // halves per A stage (128 x 40)
#define GB_ST 4352      // halves per B stage (32 x 136)
#define G_SMEM ((3 * GA_ST + 3 * GB_ST) * 2)

template <typename EpiFn>
__device__ __forceinline__ void gemm_body16(
    const __half* __restrict__ X, const __half* __restrict__ W,
    int m0, int n0, EpiFn epi)
{
    extern __shared__ __half gsm[];
    __half* As = gsm;
    __half* Bs = gsm + 3 * GA_ST;
    const uint32_t aB = smem_u32(As);
    const uint32_t bB = smem_u32(Bs);
    const int tid = threadIdx.x;
    const int lane = tid & 31, wid = tid >> 5;
    const int g = lane >> 2, t = lane & 3;
    const int mbase = (wid & 3) * 32, nbase = (wid >> 2) * 64;

    float acc[2][8][4];
#pragma unroll
    for (int mt = 0; mt < 2; mt++)
#pragma unroll
        for (int nt = 0; nt < 8; nt++)
#pragma unroll
            for (int u = 0; u < 4; u++) acc[mt][nt][u] = 0.f;

    auto issue = [&](int kt, int st) {
#pragma unroll
        for (int i = 0; i < 2; i++) {
            int idx = tid + 256 * i;
            int row = idx >> 2, off = (idx & 3) * 8;
            cp16(aB + (uint32_t)((st * GA_ST + row * 40 + off) * 2),
                 X + (size_t)(m0 + row) * DM + kt * 32 + off);
            int kr = idx >> 4, noff = (idx & 15) * 8;
            cp16(bB + (uint32_t)((st * GB_ST + kr * 136 + noff) * 2),
                 W + (size_t)(kt * 32 + kr) * DM + n0 + noff);
        }
        CP_COMMIT();
    };

    const int arow = (lane & 15);
    const int acol = ((lane >> 4) << 3);
    const int bk   = (lane & 15);
    const int bn   = ((lane >> 4) << 3);

    issue(0, 0);
    issue(1, 1);
    for (int kt = 0; kt < 32; kt++) {
        const int st = kt - (kt / 3) * 3;
        __syncthreads();
        if (kt + 2 < 32) issue(kt + 2, (kt + 2) % 3);
        else CP_COMMIT();
        CP_WAIT(2);
        __syncthreads();

        uint32_t a[2][2][4];
#pragma unroll
        for (int mt = 0; mt < 2; mt++)
#pragma unroll
            for (int kh = 0; kh < 2; kh++)
                ldsm_x4(a[mt][kh],
                        aB + (uint32_t)((st * GA_ST
                              + (mbase + mt * 16 + arow) * 40
                              + kh * 16 + acol) * 2));
#pragma unroll
        for (int kh = 0; kh < 2; kh++) {
#pragma unroll
            for (int p = 0; p < 4; p++) {
                uint32_t bf[4];
                ldsm_x4t(bf, bB + (uint32_t)((st * GB_ST
                                  + (kh * 16 + bk) * 136
                                  + nbase + p * 16 + bn) * 2));
                mma16(acc[0][2 * p],     a[0][kh], bf[0], bf[1]);
                mma16(acc[0][2 * p + 1], a[0][kh], bf[2], bf[3]);
                mma16(acc[1][2 * p],     a[1][kh], bf[0], bf[1]);
                mma16(acc[1][2 * p + 1], a[1][kh], bf[2], bf[3]);
            }
        }
    }
    epi(acc, mbase, nbase, g, t);
}

// ---------------- fused Q/K/V projection GEMM ------------------------------
__global__ __launch_bounds__(256, 2) void proj_gemm_tc(
    const float* __restrict__ Bq, const float* __restrict__ Bk, const float* __restrict__ Bv)
{
    const __half* X = g_hx[blockIdx.z];
    const __half* W = g_hw[blockIdx.z];
    const float* Bi = blockIdx.z == 0 ? Bq : blockIdx.z == 1 ? Bk : Bv;
    __half* Out = blockIdx.z == 0 ? g_q : blockIdx.z == 1 ? g_k : g_v;
    const float scale = blockIdx.z == 0 ? 0.125f : 1.0f;
    const int m0 = blockIdx.y * 128, n0 = blockIdx.x * 128;

    gemm_body16(X, W, m0, n0,
        [&](float acc[2][8][4], int mbase, int nbase, int g, int t) {
#pragma unroll
            for (int mt = 0; mt < 2; mt++) {
#pragma unroll
                for (int rr = 0; rr < 2; rr++) {
                    int m = m0 + mbase + mt * 16 + g + 8 * rr;
                    int bb = m >> 11, t_ = m & (TLEN - 1);
#pragma unroll
                    for (int nt = 0; nt < 8; nt++) {
                        int n = n0 + nbase + nt * 8 + 2 * t;
                        int h = n >> 6, d = n & 63;
                        float v0 = (acc[mt][nt][rr * 2 + 0] + Bi[n]) * scale;
                        float v1 = (acc[mt][nt][rr * 2 + 1] + Bi[n + 1]) * scale;
                        __half2* dst = (__half2*)(Out
                            + (((size_t)(bb * NH + h)) * TLEN + t_) * DK + d);
                        *dst = __floats2half2_rn(v0, v1);
                    }
                }
            }
        });
}

// ---------------- output projection GEMM (writes fp32 result) --------------
__global__ __launch_bounds__(256, 2) void out_gemm_tc(
    const float* __restrict__ Bi, float* __restrict__ Out)
{
    const int m0 = blockIdx.y * 128, n0 = blockIdx.x * 128;
    gemm_body16(g_x, g_hw[3], m0, n0,
        [&](float acc[2][8][4], int mbase, int nbase, int g, int t) {
#pragma unroll
            for (int mt = 0; mt < 2; mt++) {
#pragma unroll
                for (int rr = 0; rr < 2; rr++) {
                    int m = m0 + mbase + mt * 16 + g + 8 * rr;
#pragma unroll
                    for (int nt = 0; nt < 8; nt++) {
                        int n = n0 + nbase + nt * 8 + 2 * t;
                        float2 v;
                        v.x = acc[mt][nt][rr * 2 + 0] + Bi[n];
                        v.y = acc[mt][nt][rr * 2 + 1] + Bi[n + 1];
                        *(float2*)(Out + (size_t)m * DM + n) = v;
                    }
                }
            }
        });
}

// =============== fp16 HMMA flash attention with relative positions =========
// Br=128 (8 warps x 16 rows), Bc=64. K dbl-buffered, V single-buffered with
// late wait; f16x2 ex2 softmax on tail blocks, exact fp32 near diagonal.
#define AT_Q    0                     // 128 x 72 halves
#define AT_K    18432                 // 2 x 64 x 72 halves
#define AT_V    36864                 // 64 x 72 halves
#define AT_TBL  46080                 // 32 x 72 halves (rpr_key; rows 17..31
                                      // uninitialized -- only output cols <17
                                      // of the qr MMA are kept, B-row r feeds
                                      // only column r, so garbage is discarded)
#define AT_QR   50688                 // 128 x 17 f32 (scaled by L2E)
#define AT_RVT  59392                 // 17 x 64 f32
#define AT_SI   63744                 // 128 x 17 f32
#define AT_SMEM_BYTES 72448
#define NIT (TLEN / 64)

__global__ __launch_bounds__(256, 2) void flash_attn_tc(
    const float* __restrict__ tabk, const float* __restrict__ rvt_g)
{
    extern __shared__ char sm8[];
    const uint32_t qB = smem_u32(sm8) + AT_Q;
    const uint32_t kB = smem_u32(sm8) + AT_K;
    const uint32_t vB = smem_u32(sm8) + AT_V;
    const uint32_t tB = smem_u32(sm8) + AT_TBL;
    float* qrs  = (float*)(sm8 + AT_QR);
    float* rvts = (float*)(sm8 + AT_RVT);
    float* sInt = (float*)(sm8 + AT_SI);

    const int tid = threadIdx.x;
    const int wid = tid >> 5, lane = tid & 31;
    const int g = lane >> 2, t = lane & 3;
    const int b = blockIdx.z, h = blockIdx.y;
    const int i0 = blockIdx.x * 128;
    const size_t bh = (size_t)(b * NH + h) * TLEN;

    const int r0 = wid * 16 + g;
    const int r1 = r0 + 8;
    const int gi0 = i0 + r0, gi1 = i0 + r1;

    const __half* kgl = g_k + bh * DK;
    const __half* vgl = g_v + bh * DK;

    auto issueK = [&](int it, int st) {
        const __half* kp = kgl + (size_t)(it * 64) * DK;
#pragma unroll
        for (int i = 0; i < 2; i++) {
            int idx = tid + 256 * i;
            int row = idx >> 3, off = (idx & 7) * 8;
            cp16(kB + (uint32_t)((st * 4608 + row * 72 + off) * 2), kp + row * 64 + off);
        }
        CP_COMMIT();
    };
    auto issueV = [&](int it) {
        const __half* vp = vgl + (size_t)(it * 64) * DK;
#pragma unroll
        for (int i = 0; i < 2; i++) {
            int idx = tid + 256 * i;
            int row = idx >> 3, off = (idx & 7) * 8;
            cp16(vB + (uint32_t)((row * 72 + off) * 2), vp + row * 64 + off);
        }
        CP_COMMIT();
    };

    // prologue: Q group, K0 group; scalar tables
    {
        const __half* qp = g_q + (bh + i0) * DK;
#pragma unroll
        for (int i = 0; i < 4; i++) {
            int idx = tid + 256 * i;
            int row = idx >> 3, off = (idx & 7) * 8;
            cp16(qB + (uint32_t)((row * 72 + off) * 2), qp + row * 64 + off);
        }
        CP_COMMIT();
    }
    issueK(0, 0);
    {
        for (int idx = tid; idx < 17 * 32; idx += 256) {
            int r = idx / 32, c2 = (idx & 31) * 2;
            float2 f = *(const float2*)(tabk + r * 64 + c2);
            *(__half2*)(sm8 + AT_TBL + ((size_t)r * 72 + c2) * 2) = __floats2half2_rn(f.x, f.y);
        }
        for (int idx = tid; idx < NR * 64; idx += 256)  rvts[idx] = rvt_g[idx];
        for (int idx = tid; idx < 128 * 17; idx += 256) sInt[idx] = 0.f;
    }
    CP_WAIT(1);            // Q arrived (K0 may still be in flight)
    __syncthreads();       // Q + table visible

    const int qrow = wid * 16 + (lane & 15);
    const int qcol = ((lane >> 4) << 3);
    const int skey = ((lane >> 4) << 3) + (lane & 7);
    const int sd   = (lane & 8);
    const int vkey = (lane & 15);
    const int vd   = ((lane >> 4) << 3);

    uint32_t qa[4][4];
#pragma unroll
    for (int kh = 0; kh < 4; kh++)
        ldsm_x4(qa[kh], qB + (uint32_t)((qrow * 72 + kh * 16 + qcol) * 2));

    // qr = Q @ table^T  (n padded to 32; cols >=17 discarded)
    {
        float qracc[4][4];
#pragma unroll
        for (int p = 0; p < 4; p++)
#pragma unroll
            for (int u = 0; u < 4; u++) qracc[p][u] = 0.f;
#pragma unroll
        for (int kh = 0; kh < 4; kh++) {
#pragma unroll
            for (int p = 0; p < 2; p++) {
                uint32_t tf[4];
                ldsm_x4(tf, tB + (uint32_t)(((p * 16 + skey) * 72 + kh * 16 + sd) * 2));
                mma16(qracc[2 * p],     qa[kh], tf[0], tf[1]);
                mma16(qracc[2 * p + 1], qa[kh], tf[2], tf[3]);
            }
        }
#pragma unroll
        for (int p2 = 0; p2 < 3; p2++) {
#pragma unroll
            for (int cc = 0; cc < 2; cc++) {
                int e = p2 * 8 + 2 * t + cc;
                if (e < 17) {
                    qrs[r0 * 17 + e] = qracc[p2][cc] * L2E;
                    qrs[r1 * 17 + e] = qracc[p2][2 + cc] * L2E;
                }
            }
        }
    }
    __syncthreads();
    const float qt0_0  = qrs[r0 * 17 + 0],  qt16_0 = qrs[r0 * 17 + 16];
    const float qt0_1  = qrs[r1 * 17 + 0],  qt16_1 = qrs[r1 * 17 + 16];
    const uint32_t l2e2   = packh2(L2E, L2E);
    const uint32_t qt0h_0  = packh2(qt0_0,  qt0_0);
    const uint32_t qt16h_0 = packh2(qt16_0, qt16_0);
    const uint32_t qt0h_1  = packh2(qt0_1,  qt0_1);
    const uint32_t qt16h_1 = packh2(qt16_1, qt16_1);

    float oacc[8][4];
#pragma unroll
    for (int nt = 0; nt < 8; nt++)
#pragma unroll
        for (int u = 0; u < 4; u++) oacc[nt][u] = 0.f;
    float lsum0 = 0.f, lsum1 = 0.f;
    float b0s0 = 0.f, b0s1 = 0.f, b16s0 = 0.f, b16s1 = 0.f;

    for (int it = 0; it < NIT; it++) {
        const int j0 = it * 64;
        __syncthreads();                 // V buffer + K stage reuse safe
        issueV(it);
        if (it + 1 < NIT) { issueK(it + 1, (it + 1) & 1); CP_WAIT(2); }
        else              { CP_WAIT(1); }
        __syncthreads();                 // K(it) ready

        const uint32_t kS = kB + (uint32_t)((it & 1) * 4608 * 2);

        // S = Q @ K^T
        float sacc[8][4];
#pragma unroll
        for (int nt = 0; nt < 8; nt++)
#pragma unroll
            for (int u = 0; u < 4; u++) sacc[nt][u] = 0.f;
#pragma unroll
        for (int kh = 0; kh < 4; kh++) {
#pragma unroll
            for (int p = 0; p < 4; p++) {
                uint32_t bf[4];
                ldsm_x4(bf, kS + (uint32_t)(((p * 16 + skey) * 72
                                 + kh * 16 + sd) * 2));
                mma16(sacc[2 * p],     qa[kh], bf[0], bf[1]);
                mma16(sacc[2 * p + 1], qa[kh], bf[2], bf[3]);
            }
        }

        // softmax; f16x2 ex2 on tail blocks, exact fp32 near diagonal
        uint32_t ep[8][2];
        // ---- row 0
        if (j0 + 71 <= gi0 || j0 >= gi0 + 8) {
            const bool left = (j0 + 71 <= gi0);
            const uint32_t qth = left ? qt0h_0 : qt16h_0;
            float bs = 0.f;
#pragma unroll
            for (int nt = 0; nt < 8; nt++) {
                uint32_t ph = packh2(sacc[nt][1], sacc[nt][0]);
                uint32_t pe = ex2h2(hfma2u(ph, l2e2, qth));
                ep[nt][0] = pe;
                float2 pf = h22f2(pe);
                bs += pf.x + pf.y;
            }
            lsum0 += bs;
            if (left) b0s0 += bs; else b16s0 += bs;
        } else {
#pragma unroll
            for (int nt = 0; nt < 8; nt++) {
                float pv[2];
#pragma unroll
                for (int cc = 0; cc < 2; cc++) {
                    const int j = j0 + nt * 8 + 2 * t + cc;
                    int dd = j - gi0;
                    float add = (dd <= -8) ? qt0_0 : (dd >= 8) ? qt16_0
                                : qrs[r0 * 17 + dd + 8];
                    float p = exp2f(fmaf(sacc[nt][cc], L2E, add));
                    lsum0 += p;
                    if (dd <= -8)      b0s0 += p;
                    else if (dd >= 8)  b16s0 += p;
                    else               sInt[r0 * 17 + dd + 7] = p;
                    pv[cc] = p;
                }
                ep[nt][0] = packh2(pv[1], pv[0]);
            }
        }
        // ---- row 1
        if (j0 + 71 <= gi1 || j0 >= gi1 + 8) {
            const bool left = (j0 + 71 <= gi1);
            const uint32_t qth = left ? qt0h_1 : qt16h_1;
            float bs = 0.f;
#pragma unroll
            for (int nt = 0; nt < 8; nt++) {
                uint32_t ph = packh2(sacc[nt][3], sacc[nt][2]);
                uint32_t pe = ex2h2(hfma2u(ph, l2e2, qth));
                ep[nt][1] = pe;
                float2 pf = h22f2(pe);
                bs += pf.x + pf.y;
            }
            lsum1 += bs;
            if (left) b0s1 += bs; else b16s1 += bs;
        } else {
#pragma unroll
            for (int nt = 0; nt < 8; nt++) {
                float pv[2];
#pragma unroll
                for (int cc = 0; cc < 2; cc++) {
                    const int j = j0 + nt * 8 + 2 * t + cc;
                    int dd = j - gi1;
                    float add = (dd <= -8) ? qt0_1 : (dd >= 8) ? qt16_1
                                : qrs[r1 * 17 + dd + 8];
                    float p = exp2f(fmaf(sacc[nt][2 + cc], L2E, add));
                    lsum1 += p;
                    if (dd <= -8)      b0s1 += p;
                    else if (dd >= 8)  b16s1 += p;
                    else               sInt[r1 * 17 + dd + 7] = p;
                    pv[cc] = p;
                }
                ep[nt][1] = packh2(pv[1], pv[0]);
            }
        }

        if (it + 1 < NIT) CP_WAIT(1); else CP_WAIT(0);
        __syncthreads();                 // V(it) ready

        // O += P @ V  (ep pairs ARE the A-fragments)
#pragma unroll
        for (int ks = 0; ks < 4; ks++) {
            uint32_t pa[4];
            pa[0] = ep[2 * ks][0];
            pa[1] = ep[2 * ks][1];
            pa[2] = ep[2 * ks + 1][0];
            pa[3] = ep[2 * ks + 1][1];
#pragma unroll
            for (int p = 0; p < 4; p++) {
                uint32_t bf[4];
                ldsm_x4t(bf, vB + (uint32_t)(((ks * 16 + vkey) * 72
                                  + p * 16 + vd) * 2));
                mma16(oacc[2 * p],     pa, bf[0], bf[1]);
                mma16(oacc[2 * p + 1], pa, bf[2], bf[3]);
            }
        }
    }

    __syncthreads();
#pragma unroll
    for (int o = 1; o <= 2; o <<= 1) {
        lsum0 += __shfl_xor_sync(0xffffffffu, lsum0, o);
        lsum1 += __shfl_xor_sync(0xffffffffu, lsum1, o);
        b0s0  += __shfl_xor_sync(0xffffffffu, b0s0, o);
        b0s1  += __shfl_xor_sync(0xffffffffu, b0s1, o);
        b16s0 += __shfl_xor_sync(0xffffffffu, b16s0, o);
        b16s1 += __shfl_xor_sync(0xffffffffu, b16s1, o);
    }
    const float linv0 = 1.0f / lsum0, linv1 = 1.0f / lsum1;

    float si0[15], si1[15];
#pragma unroll
    for (int e = 0; e < 15; e++) {
        si0[e] = sInt[r0 * 17 + e];
        si1[e] = sInt[r1 * 17 + e];
    }

    __half* op0 = g_x + ((size_t)(b * TLEN) + gi0) * DM + h * DK;
    __half* op1 = g_x + ((size_t)(b * TLEN) + gi1) * DM + h * DK;
#pragma unroll
    for (int nt = 0; nt < 8; nt++) {
        const int d = nt * 8 + 2 * t;
        float e0a = b0s0 * rvts[d]     + b16s0 * rvts[16 * 64 + d];
        float e0b = b0s0 * rvts[d + 1] + b16s0 * rvts[16 * 64 + d + 1];
        float e1a = b0s1 * rvts[d]     + b16s1 * rvts[16 * 64 + d];
        float e1b = b0s1 * rvts[d + 1] + b16s1 * rvts[16 * 64 + d + 1];
#pragma unroll
        for (int e = 1; e <= 15; e++) {
            float rva = rvts[e * 64 + d], rvb = rvts[e * 64 + d + 1];
            e0a += si0[e - 1] * rva;  e0b += si0[e - 1] * rvb;
            e1a += si1[e - 1] * rva;  e1b += si1[e - 1] * rvb;
        }
        *(__half2*)(op0 + d) = __floats2half2_rn(
            (oacc[nt][0] + e0a) * linv0, (oacc[nt][1] + e0b) * linv0);
        *(__half2*)(op1 + d) = __floats2half2_rn(
            (oacc[nt][2] + e1a) * linv1, (oacc[nt][3] + e1b) * linv1);
    }
}

// ---------------- launch ----------------------------------------------------
extern "C" void kernel_launch(void* const* d_in, const int* in_sizes, int n_in,
                              void* d_out, int out_size)
{
    const float* query = (const float*)d_in[0];
    const float* key_  = (const float*)d_in[1];
    const float* value = (const float*)d_in[2];
    const float* w_q = (const float*)d_in[4];
    const float* b_q = (const float*)d_in[5];
    const float* w_k = (const float*)d_in[6];
    const float* b_k = (const float*)d_in[7];
    const float* w_v = (const float*)d_in[8];
    const float* b_v = (const float*)d_in[9];
    const float* w_o = (const float*)d_in[10];
    const float* b_o = (const float*)d_in[11];
    const float* rpr_k = (const float*)d_in[12];
    const float* rpr_v = (const float*)d_in[13];
    float* out = (float*)d_out;

    cudaFuncSetAttribute(proj_gemm_tc, cudaFuncAttributeMaxDynamicSharedMemorySize, G_SMEM);
    cudaFuncSetAttribute(out_gemm_tc,  cudaFuncAttributeMaxDynamicSharedMemorySize, G_SMEM);
    cudaFuncSetAttribute(flash_attn_tc, cudaFuncAttributeMaxDynamicSharedMemorySize, AT_SMEM_BYTES);

    cvt_all<<<3 * CVT_XBLK + 4 * CVT_WBLK, 256>>>(
        query, key_, value, w_q, w_k, w_v, w_o);

    proj_gemm_tc<<<dim3(DM / 128, (BSZ * TLEN) / 128, 3), 256, G_SMEM>>>(b_q, b_k, b_v);

    flash_attn_tc<<<dim3(TLEN / 128, NH, BSZ), 256, AT_SMEM_BYTES>>>(rpr_k, rpr_v);

    out_gemm_tc<<<dim3(DM / 128, (BSZ * TLEN) / 128, 1), 256, G_SMEM>>>(b_o, out);
}